// round 5
// baseline (speedup 1.0000x reference)
#include <cuda_runtime.h>
#include <cstdint>

#define B 2048
#define T 128
#define C 192
#define H 96
#define NC 38
#define S 25
#define J3H 288        // 3*H
#define KX 230         // C + NC
#define GB 16          // batch items per GRU block

// ---------------- device scratch (no allocations allowed) ----------------
__device__ float g_Hproj[(size_t)B * T * H];   // ~100 MB
__device__ float g_ctx[B * C];
__device__ float g_h[B * H];
__device__ float g_WT_i2h[C * H];              // [c][h]
__device__ float g_WT_h2h[H * H];              // [k][h]
__device__ float g_WT_ih[KX * J3H];            // [k][j]
__device__ float g_WT_hh[H * J3H];             // [k][j]
__device__ float g_WT_gen[H * NC];             // [h][nc]
__device__ int   g_is64;

// ---------------- fast math helpers ----------------
__device__ __forceinline__ float tanh_fast(float x) {
    x = fminf(fmaxf(x, -10.f), 10.f);
    float e = __expf(2.f * x);
    return __fdividef(e - 1.f, e + 1.f);
}
__device__ __forceinline__ float sigmoid_fast(float x) {
    return __fdividef(1.f, 1.f + __expf(-x));
}

// ---------------- prep: transposes + h zero + targets dtype probe ----------------
__global__ void prep_kernel(const float* __restrict__ w_i2h,
                            const float* __restrict__ w_h2h,
                            const float* __restrict__ w_ih,
                            const float* __restrict__ w_hh,
                            const float* __restrict__ w_gen,
                            const void*  __restrict__ targets_raw) {
    int i0 = blockIdx.x * blockDim.x + threadIdx.x;
    int stride = gridDim.x * blockDim.x;
    for (int i = i0; i < H * C; i += stride) { int h = i / C, c = i % C; g_WT_i2h[c * H + h] = w_i2h[i]; }
    for (int i = i0; i < H * H; i += stride) { int h = i / H, k = i % H; g_WT_h2h[k * H + h] = w_h2h[i]; }
    for (int i = i0; i < J3H * KX; i += stride) { int j = i / KX, k = i % KX; g_WT_ih[k * J3H + j] = w_ih[i]; }
    for (int i = i0; i < J3H * H; i += stride) { int j = i / H, k = i % H; g_WT_hh[k * J3H + j] = w_hh[i]; }
    for (int i = i0; i < NC * H; i += stride) { int n = i / H, h = i % H; g_WT_gen[h * NC + n] = w_gen[i]; }
    for (int i = i0; i < B * H; i += stride) g_h[i] = 0.f;
    if (i0 == 0) {
        // Detect int64 vs int32 targets: int64 class indices are all in [0, NC).
        const long long* t64 = (const long long*)targets_raw;
        int ok = 1;
        for (int q = 0; q < 64; q++) {
            long long v = t64[q];
            if (v < 0 || v >= NC) { ok = 0; break; }
        }
        g_is64 = ok;
    }
}

// ---------------- Hproj = inputs @ w_i2h^T  ([B*T, H]) ----------------
#define HP_ROWS 64
#define HP_CK   64
__global__ void __launch_bounds__(256) hproj_kernel(const float* __restrict__ inputs) {
    __shared__ __align__(16) float in_s[HP_ROWS][HP_CK];
    __shared__ __align__(16) float wt_s[HP_CK][H];
    int tid = threadIdx.x;
    int tx = tid & 31, ty = tid >> 5;
    int rowbase = blockIdx.x * HP_ROWS;

    float acc[8][3];
#pragma unroll
    for (int r = 0; r < 8; r++)
#pragma unroll
        for (int k = 0; k < 3; k++) acc[r][k] = 0.f;

    for (int c0 = 0; c0 < C; c0 += HP_CK) {
        const float4* wsrc = (const float4*)(g_WT_i2h + c0 * H);
        for (int idx = tid; idx < HP_CK * H / 4; idx += 256)
            ((float4*)wt_s)[idx] = wsrc[idx];
        for (int idx = tid; idx < HP_ROWS * HP_CK / 4; idx += 256) {
            int r = idx >> 4;   // 16 float4 per row
            int q = idx & 15;
            float4 v = *(const float4*)(inputs + (size_t)(rowbase + r) * C + c0 + q * 4);
            *(float4*)&in_s[r][q * 4] = v;
        }
        __syncthreads();
#pragma unroll 2
        for (int cc = 0; cc < HP_CK; ++cc) {
            float w0 = wt_s[cc][tx * 3 + 0];
            float w1 = wt_s[cc][tx * 3 + 1];
            float w2 = wt_s[cc][tx * 3 + 2];
#pragma unroll
            for (int r = 0; r < 8; r++) {
                float iv = in_s[ty * 8 + r][cc];
                acc[r][0] += iv * w0;
                acc[r][1] += iv * w1;
                acc[r][2] += iv * w2;
            }
        }
        __syncthreads();
    }
#pragma unroll
    for (int r = 0; r < 8; r++) {
        float* dst = g_Hproj + (size_t)(rowbase + ty * 8 + r) * H + tx * 3;
        dst[0] = acc[r][0]; dst[1] = acc[r][1]; dst[2] = acc[r][2];
    }
}

// ---------------- per-step attention: context[b] from h[b] ----------------
__global__ void __launch_bounds__(256) att_kernel(const float* __restrict__ inputs,
                                                  const float* __restrict__ b_h2h,
                                                  const float* __restrict__ w_score) {
    __shared__ float h_s[H], hp_s[H], sv_s[H];
    __shared__ float e_s[T], alpha_s[T], red[T];
    int tid = threadIdx.x;
    int b = blockIdx.x;

    if (tid < H) { h_s[tid] = g_h[b * H + tid]; sv_s[tid] = w_score[tid]; }
    __syncthreads();

    // hp = h @ w_h2h^T + b_h2h
    if (tid < H) {
        float acc = b_h2h[tid];
#pragma unroll 4
        for (int k = 0; k < H; k++) acc += g_WT_h2h[k * H + tid] * h_s[k];
        hp_s[tid] = acc;
    }
    __syncthreads();

    // e[t] = sum_h sv[h] * tanh(Hproj[b,t,h] + hp[h]); warp-per-t, lanes along h
    int w = tid >> 5, l = tid & 31;
    const float* hb = g_Hproj + (size_t)b * T * H;
    for (int i = 0; i < 16; i++) {
        int t = w * 16 + i;
        const float* row = hb + t * H;
        float x0 = row[l]      + hp_s[l];
        float x1 = row[l + 32] + hp_s[l + 32];
        float x2 = row[l + 64] + hp_s[l + 64];
        float v = sv_s[l]      * tanh_fast(x0)
                + sv_s[l + 32] * tanh_fast(x1)
                + sv_s[l + 64] * tanh_fast(x2);
#pragma unroll
        for (int off = 16; off > 0; off >>= 1) v += __shfl_xor_sync(0xffffffffu, v, off);
        if (l == 0) e_s[t] = v;
    }
    __syncthreads();

    // softmax over T=128
    if (tid < T) red[tid] = e_s[tid];
    __syncthreads();
    for (int off = 64; off > 0; off >>= 1) {
        if (tid < off) red[tid] = fmaxf(red[tid], red[tid + off]);
        __syncthreads();
    }
    float mx = red[0];
    __syncthreads();
    if (tid < T) { float p = __expf(e_s[tid] - mx); alpha_s[tid] = p; red[tid] = p; }
    __syncthreads();
    for (int off = 64; off > 0; off >>= 1) {
        if (tid < off) red[tid] += red[tid + off];
        __syncthreads();
    }
    float inv = __fdividef(1.f, red[0]);
    __syncthreads();
    if (tid < T) alpha_s[tid] *= inv;
    __syncthreads();

    // context[c] = sum_t alpha[t] * inputs[b,t,c]
    if (tid < C) {
        const float* ip = inputs + (size_t)b * T * C + tid;
        float acc = 0.f;
#pragma unroll 4
        for (int t = 0; t < T; t++) acc += alpha_s[t] * ip[t * C];
        g_ctx[b * C + tid] = acc;
    }
}

// ---------------- per-step GRU + generator, 16 batch items per block ----------------
#define FMA16(ACC, WV, PTR) do {                                          \
    const float4* _p = (const float4*)(PTR);                              \
    float4 _a = _p[0], _b = _p[1], _c = _p[2], _d = _p[3];                \
    ACC[0]  += (WV) * _a.x; ACC[1]  += (WV) * _a.y;                       \
    ACC[2]  += (WV) * _a.z; ACC[3]  += (WV) * _a.w;                       \
    ACC[4]  += (WV) * _b.x; ACC[5]  += (WV) * _b.y;                       \
    ACC[6]  += (WV) * _b.z; ACC[7]  += (WV) * _b.w;                       \
    ACC[8]  += (WV) * _c.x; ACC[9]  += (WV) * _c.y;                       \
    ACC[10] += (WV) * _c.z; ACC[11] += (WV) * _c.w;                       \
    ACC[12] += (WV) * _d.x; ACC[13] += (WV) * _d.y;                       \
    ACC[14] += (WV) * _d.z; ACC[15] += (WV) * _d.w;                       \
} while (0)

__global__ void __launch_bounds__(288) gru_kernel(const void* __restrict__ targets_raw,
                                                  const float* __restrict__ b_ih,
                                                  const float* __restrict__ b_hh,
                                                  const float* __restrict__ b_gen,
                                                  float* __restrict__ probs, int s) {
    __shared__ __align__(16) float xsT[C][GB];     // context, transposed
    __shared__ __align__(16) float hsT[H][GB];     // h (then h_new), transposed
    __shared__ float Ssum[GB][2 * H];              // gi+gh for r,z gates
    __shared__ float INs[GB][H];                   // i_n
    __shared__ float HNs[GB][H];                   // h_n (gh part)
    __shared__ int cls_s[GB];

    int tid = threadIdx.x;
    int b0 = blockIdx.x * GB;

    for (int idx = tid; idx < GB * C; idx += J3H) { int bb = idx / C, k = idx % C; xsT[k][bb] = g_ctx[(b0 + bb) * C + k]; }
    for (int idx = tid; idx < GB * H; idx += J3H) { int bb = idx / H, k = idx % H; hsT[k][bb] = g_h[(b0 + bb) * H + k]; }
    if (tid < GB) {
        int cls;
        if (g_is64) cls = (int)((const long long*)targets_raw)[(size_t)(b0 + tid) * S + s];
        else        cls = ((const int*)targets_raw)[(size_t)(b0 + tid) * S + s];
        cls_s[tid] = cls;
    }
    __syncthreads();

    int j = tid;  // 0..287
    float accI[GB], accH[GB];
    float bI = b_ih[j], bH = b_hh[j];
#pragma unroll
    for (int bb = 0; bb < GB; bb++) accI[bb] = bI + g_WT_ih[(C + cls_s[bb]) * J3H + j];  // one-hot column
#pragma unroll
    for (int bb = 0; bb < GB; bb++) accH[bb] = bH;

#pragma unroll 2
    for (int k = 0; k < C; k++) {
        float wv = g_WT_ih[k * J3H + j];
        FMA16(accI, wv, &xsT[k][0]);
    }
#pragma unroll 2
    for (int k = 0; k < H; k++) {
        float wv = g_WT_hh[k * J3H + j];
        FMA16(accH, wv, &hsT[k][0]);
    }

    if (j < 2 * H) {
#pragma unroll
        for (int bb = 0; bb < GB; bb++) Ssum[bb][j] = accI[bb] + accH[bb];
    } else {
        int jj = j - 2 * H;
#pragma unroll
        for (int bb = 0; bb < GB; bb++) { INs[bb][jj] = accI[bb]; HNs[bb][jj] = accH[bb]; }
    }
    __syncthreads();

    // gates + h update
    for (int idx = tid; idx < GB * H; idx += J3H) {
        int bb = idx / H, h = idx % H;
        float r = sigmoid_fast(Ssum[bb][h]);
        float z = sigmoid_fast(Ssum[bb][H + h]);
        float n = tanh_fast(INs[bb][h] + r * HNs[bb][h]);
        float hn = (1.f - z) * n + z * hsT[h][bb];
        g_h[(b0 + bb) * H + h] = hn;
        hsT[h][bb] = hn;   // own slot: read-then-write, race-free
    }
    __syncthreads();

    // generator: probs[b,s,:] = h_new @ w_gen^T + b_gen
    for (int idx = tid; idx < GB * NC; idx += J3H) {
        int bb = idx / NC, nc = idx % NC;
        float acc = b_gen[nc];
#pragma unroll 4
        for (int h = 0; h < H; h++) acc += g_WT_gen[h * NC + nc] * hsT[h][bb];
        probs[(size_t)((b0 + bb) * S + s) * NC + nc] = acc;
    }
}

// ---------------- launch ----------------
extern "C" void kernel_launch(void* const* d_in, const int* in_sizes, int n_in,
                              void* d_out, int out_size) {
    const float* inputs  = (const float*)d_in[0];
    const void*  targets = d_in[1];
    const float* w_i2h   = (const float*)d_in[2];
    const float* w_h2h   = (const float*)d_in[3];
    const float* b_h2h   = (const float*)d_in[4];
    const float* w_score = (const float*)d_in[5];
    const float* w_ih    = (const float*)d_in[6];
    const float* w_hh    = (const float*)d_in[7];
    const float* b_ih    = (const float*)d_in[8];
    const float* b_hh    = (const float*)d_in[9];
    const float* w_gen   = (const float*)d_in[10];
    const float* b_gen   = (const float*)d_in[11];
    float* probs = (float*)d_out;

    prep_kernel<<<256, 256>>>(w_i2h, w_h2h, w_ih, w_hh, w_gen, targets);
    hproj_kernel<<<(B * T) / HP_ROWS, 256>>>(inputs);
    for (int s = 0; s < S; s++) {
        att_kernel<<<B, 256>>>(inputs, b_h2h, w_score);
        gru_kernel<<<B / GB, J3H>>>(targets, b_ih, b_hh, b_gen, probs, s);
    }
}

// round 8
// speedup vs baseline: 1.1983x; 1.1983x over previous
#include <cuda_runtime.h>
#include <cstdint>

#define B 2048
#define T 128
#define C 192
#define H 96
#define NC 38
#define S 25
#define J3H 288        // 3*H
#define KX 230         // C + NC
#define GB 8           // batch items per GRU block

// ---------------- device scratch (no allocations allowed) ----------------
__device__ float g_Hproj[(size_t)B * T * H];   // ~100 MB
__device__ float g_ctx[B * C];
__device__ float g_h[B * H];
__device__ float g_hp[B * H];                  // h @ w_h2h^T + b_h2h, for NEXT att step
__device__ float g_WT_i2h[C * H];              // [c][h]
__device__ float g_WT_h2h[H * H];              // [k][h]
__device__ float g_WT_ih[KX * J3H];            // [k][j]
__device__ float g_WT_hh[H * J3H];             // [k][j]
__device__ float g_WT_gen[H * NC];             // [h][nc]
__device__ int   g_is64;

// ---------------- fast math helpers ----------------
__device__ __forceinline__ float tanh_fast(float x) {
    x = fminf(fmaxf(x, -10.f), 10.f);
    float e = __expf(2.f * x);
    return __fdividef(e - 1.f, e + 1.f);
}
__device__ __forceinline__ float sigmoid_fast(float x) {
    return __fdividef(1.f, 1.f + __expf(-x));
}

// ---------------- prep: transposes + h/hp init + targets dtype probe ----------------
__global__ void prep_kernel(const float* __restrict__ w_i2h,
                            const float* __restrict__ w_h2h,
                            const float* __restrict__ b_h2h,
                            const float* __restrict__ w_ih,
                            const float* __restrict__ w_hh,
                            const float* __restrict__ w_gen,
                            const void*  __restrict__ targets_raw) {
    int i0 = blockIdx.x * blockDim.x + threadIdx.x;
    int stride = gridDim.x * blockDim.x;
    for (int i = i0; i < H * C; i += stride) { int h = i / C, c = i % C; g_WT_i2h[c * H + h] = w_i2h[i]; }
    for (int i = i0; i < H * H; i += stride) { int h = i / H, k = i % H; g_WT_h2h[k * H + h] = w_h2h[i]; }
    for (int i = i0; i < J3H * KX; i += stride) { int j = i / KX, k = i % KX; g_WT_ih[k * J3H + j] = w_ih[i]; }
    for (int i = i0; i < J3H * H; i += stride) { int j = i / H, k = i % H; g_WT_hh[k * J3H + j] = w_hh[i]; }
    for (int i = i0; i < NC * H; i += stride) { int n = i / H, h = i % H; g_WT_gen[h * NC + n] = w_gen[i]; }
    for (int i = i0; i < B * H; i += stride) { g_h[i] = 0.f; g_hp[i] = b_h2h[i % H]; }
    if (i0 == 0) {
        // Detect int64 vs int32 targets: valid int64 class indices are all in [0, NC).
        const long long* t64 = (const long long*)targets_raw;
        int ok = 1;
        for (int q = 0; q < 64; q++) {
            long long v = t64[q];
            if (v < 0 || v >= NC) { ok = 0; break; }
        }
        g_is64 = ok;
    }
}

// ---------------- Hproj = inputs @ w_i2h^T  ([B*T, H]) ----------------
#define HP_ROWS 64
#define HP_CK   64
__global__ void __launch_bounds__(256) hproj_kernel(const float* __restrict__ inputs) {
    __shared__ __align__(16) float in_s[HP_ROWS][HP_CK];
    __shared__ __align__(16) float wt_s[HP_CK][H];
    int tid = threadIdx.x;
    int tx = tid & 31, ty = tid >> 5;
    int rowbase = blockIdx.x * HP_ROWS;

    float acc[8][3];
#pragma unroll
    for (int r = 0; r < 8; r++)
#pragma unroll
        for (int k = 0; k < 3; k++) acc[r][k] = 0.f;

    for (int c0 = 0; c0 < C; c0 += HP_CK) {
        const float4* wsrc = (const float4*)(g_WT_i2h + c0 * H);
        for (int idx = tid; idx < HP_CK * H / 4; idx += 256)
            ((float4*)wt_s)[idx] = wsrc[idx];
        for (int idx = tid; idx < HP_ROWS * HP_CK / 4; idx += 256) {
            int r = idx >> 4;   // 16 float4 per row
            int q = idx & 15;
            float4 v = *(const float4*)(inputs + (size_t)(rowbase + r) * C + c0 + q * 4);
            *(float4*)&in_s[r][q * 4] = v;
        }
        __syncthreads();
#pragma unroll 2
        for (int cc = 0; cc < HP_CK; ++cc) {
            float w0 = wt_s[cc][tx * 3 + 0];
            float w1 = wt_s[cc][tx * 3 + 1];
            float w2 = wt_s[cc][tx * 3 + 2];
#pragma unroll
            for (int r = 0; r < 8; r++) {
                float iv = in_s[ty * 8 + r][cc];
                acc[r][0] += iv * w0;
                acc[r][1] += iv * w1;
                acc[r][2] += iv * w2;
            }
        }
        __syncthreads();
    }
#pragma unroll
    for (int r = 0; r < 8; r++) {
        float* dst = g_Hproj + (size_t)(rowbase + ty * 8 + r) * H + tx * 3;
        dst[0] = acc[r][0]; dst[1] = acc[r][1]; dst[2] = acc[r][2];
    }
}

// ---------------- per-step attention: context[b] from precomputed hp[b] ----------------
__global__ void __launch_bounds__(256) att_kernel(const float* __restrict__ inputs,
                                                  const float* __restrict__ w_score) {
    __shared__ float hp_s[H], sv_s[H];
    __shared__ float e_s[T], alpha_s[T], red[T];
    int tid = threadIdx.x;
    int b = blockIdx.x;

    if (tid < H) { hp_s[tid] = g_hp[b * H + tid]; sv_s[tid] = w_score[tid]; }
    __syncthreads();

    // e[t] = sum_h sv[h] * tanh(Hproj[b,t,h] + hp[h]); warp-per-t, lanes along h
    int w = tid >> 5, l = tid & 31;
    const float* hb = g_Hproj + (size_t)b * T * H;
    for (int i = 0; i < 16; i++) {
        int t = w * 16 + i;
        const float* row = hb + t * H;
        float x0 = row[l]      + hp_s[l];
        float x1 = row[l + 32] + hp_s[l + 32];
        float x2 = row[l + 64] + hp_s[l + 64];
        float v = sv_s[l]      * tanh_fast(x0)
                + sv_s[l + 32] * tanh_fast(x1)
                + sv_s[l + 64] * tanh_fast(x2);
#pragma unroll
        for (int off = 16; off > 0; off >>= 1) v += __shfl_xor_sync(0xffffffffu, v, off);
        if (l == 0) e_s[t] = v;
    }
    __syncthreads();

    // softmax over T=128
    if (tid < T) red[tid] = e_s[tid];
    __syncthreads();
    for (int off = 64; off > 0; off >>= 1) {
        if (tid < off) red[tid] = fmaxf(red[tid], red[tid + off]);
        __syncthreads();
    }
    float mx = red[0];
    __syncthreads();
    if (tid < T) { float p = __expf(e_s[tid] - mx); alpha_s[tid] = p; red[tid] = p; }
    __syncthreads();
    for (int off = 64; off > 0; off >>= 1) {
        if (tid < off) red[tid] += red[tid + off];
        __syncthreads();
    }
    float inv = __fdividef(1.f, red[0]);
    __syncthreads();
    if (tid < T) alpha_s[tid] *= inv;
    __syncthreads();

    // context[c] = sum_t alpha[t] * inputs[b,t,c]
    if (tid < C) {
        const float* ip = inputs + (size_t)b * T * C + tid;
        float acc = 0.f;
#pragma unroll 4
        for (int t = 0; t < T; t++) acc += alpha_s[t] * ip[t * C];
        g_ctx[b * C + tid] = acc;
    }
}

// ---------------- per-step GRU + generator + next-step hp, 8 batch items per block ----------------
#define FMA8(ACC, WV, PTR) do {                                           \
    const float4* _p = (const float4*)(PTR);                              \
    float4 _a = _p[0], _b = _p[1];                                        \
    ACC[0] += (WV) * _a.x; ACC[1] += (WV) * _a.y;                         \
    ACC[2] += (WV) * _a.z; ACC[3] += (WV) * _a.w;                         \
    ACC[4] += (WV) * _b.x; ACC[5] += (WV) * _b.y;                         \
    ACC[6] += (WV) * _b.z; ACC[7] += (WV) * _b.w;                         \
} while (0)

__global__ void __launch_bounds__(288) gru_kernel(const void* __restrict__ targets_raw,
                                                  const float* __restrict__ b_ih,
                                                  const float* __restrict__ b_hh,
                                                  const float* __restrict__ b_h2h,
                                                  const float* __restrict__ b_gen,
                                                  float* __restrict__ probs, int s) {
    __shared__ __align__(16) float xsT[C][GB];     // context, transposed
    __shared__ __align__(16) float hsT[H][GB];     // h (then h_new), transposed
    __shared__ float Ssum[GB][2 * H];              // gi+gh for r,z gates
    __shared__ float INs[GB][H];                   // i_n
    __shared__ float HNs[GB][H];                   // h_n (gh part)
    __shared__ int cls_s[GB];

    int tid = threadIdx.x;
    int b0 = blockIdx.x * GB;

    for (int idx = tid; idx < GB * C; idx += J3H) { int bb = idx / C, k = idx % C; xsT[k][bb] = g_ctx[(b0 + bb) * C + k]; }
    for (int idx = tid; idx < GB * H; idx += J3H) { int bb = idx / H, k = idx % H; hsT[k][bb] = g_h[(b0 + bb) * H + k]; }
    if (tid < GB) {
        int cls;
        if (g_is64) cls = (int)((const long long*)targets_raw)[(size_t)(b0 + tid) * S + s];
        else        cls = ((const int*)targets_raw)[(size_t)(b0 + tid) * S + s];
        cls_s[tid] = cls;
    }
    __syncthreads();

    int j = tid;  // 0..287
    float accI[GB], accH[GB];
    float bI = b_ih[j], bH = b_hh[j];
#pragma unroll
    for (int bb = 0; bb < GB; bb++) accI[bb] = bI + g_WT_ih[(C + cls_s[bb]) * J3H + j];  // one-hot column
#pragma unroll
    for (int bb = 0; bb < GB; bb++) accH[bb] = bH;

    // input GEMM, 8-deep weight prefetch pipeline (MLP=8)
    {
        const float* Wp = g_WT_ih + j;
#pragma unroll 1
        for (int k0 = 0; k0 < C; k0 += 8) {
            float w[8];
#pragma unroll
            for (int u = 0; u < 8; u++) w[u] = Wp[(k0 + u) * J3H];
#pragma unroll
            for (int u = 0; u < 8; u++) FMA8(accI, w[u], &xsT[k0 + u][0]);
        }
    }
    // hidden GEMM
    {
        const float* Wp = g_WT_hh + j;
#pragma unroll 1
        for (int k0 = 0; k0 < H; k0 += 8) {
            float w[8];
#pragma unroll
            for (int u = 0; u < 8; u++) w[u] = Wp[(k0 + u) * J3H];
#pragma unroll
            for (int u = 0; u < 8; u++) FMA8(accH, w[u], &hsT[k0 + u][0]);
        }
    }

    if (j < 2 * H) {
#pragma unroll
        for (int bb = 0; bb < GB; bb++) Ssum[bb][j] = accI[bb] + accH[bb];
    } else {
        int jj = j - 2 * H;
#pragma unroll
        for (int bb = 0; bb < GB; bb++) { INs[bb][jj] = accI[bb]; HNs[bb][jj] = accH[bb]; }
    }
    __syncthreads();

    // gates + h update
    for (int idx = tid; idx < GB * H; idx += J3H) {
        int bb = idx / H, h = idx % H;
        float r = sigmoid_fast(Ssum[bb][h]);
        float z = sigmoid_fast(Ssum[bb][H + h]);
        float n = tanh_fast(INs[bb][h] + r * HNs[bb][h]);
        float hn = (1.f - z) * n + z * hsT[h][bb];
        g_h[(b0 + bb) * H + h] = hn;
        hsT[h][bb] = hn;   // own slot: read-then-write, race-free
    }
    __syncthreads();

    // generator: probs[b,s,:] = h_new @ w_gen^T + b_gen
    for (int idx = tid; idx < GB * NC; idx += J3H) {
        int bb = idx / NC, nc = idx % NC;
        float acc = b_gen[nc];
#pragma unroll 4
        for (int h = 0; h < H; h++) acc += g_WT_gen[h * NC + nc] * hsT[h][bb];
        probs[(size_t)((b0 + bb) * S + s) * NC + nc] = acc;
    }

    // next-step hp: hp[b] = h_new @ w_h2h^T + b_h2h  (hoisted out of att)
    for (int idx = tid; idx < GB * H; idx += J3H) {
        int bb = idx / H, h = idx % H;
        float acc = b_h2h[h];
#pragma unroll 4
        for (int k = 0; k < H; k++) acc += g_WT_h2h[k * H + h] * hsT[k][bb];
        g_hp[(b0 + bb) * H + h] = acc;
    }
}

// ---------------- launch ----------------
extern "C" void kernel_launch(void* const* d_in, const int* in_sizes, int n_in,
                              void* d_out, int out_size) {
    const float* inputs  = (const float*)d_in[0];
    const void*  targets = d_in[1];
    const float* w_i2h   = (const float*)d_in[2];
    const float* w_h2h   = (const float*)d_in[3];
    const float* b_h2h   = (const float*)d_in[4];
    const float* w_score = (const float*)d_in[5];
    const float* w_ih    = (const float*)d_in[6];
    const float* w_hh    = (const float*)d_in[7];
    const float* b_ih    = (const float*)d_in[8];
    const float* b_hh    = (const float*)d_in[9];
    const float* w_gen   = (const float*)d_in[10];
    const float* b_gen   = (const float*)d_in[11];
    float* probs = (float*)d_out;

    prep_kernel<<<148, 256>>>(w_i2h, w_h2h, b_h2h, w_ih, w_hh, w_gen, targets);
    hproj_kernel<<<(B * T) / HP_ROWS, 256>>>(inputs);
    for (int s = 0; s < S; s++) {
        att_kernel<<<B, 256>>>(inputs, w_score);
        gru_kernel<<<B / GB, J3H>>>(targets, b_ih, b_hh, b_h2h, b_gen, probs, s);
    }
}

// round 9
// speedup vs baseline: 1.4539x; 1.2133x over previous
#include <cuda_runtime.h>
#include <cuda_fp16.h>
#include <cstdint>

#define B 2048
#define T 128
#define C 192
#define H 96
#define NC 38
#define S 25
#define J3H 288        // 3*H
#define KX 230         // C + NC
#define GB 8           // batch items per GRU block

// ---------------- device scratch (no allocations allowed) ----------------
__device__ __half g_Hproj_h[(size_t)B * T * H];   // 50 MB fp16
__device__ __half g_in_h[(size_t)B * T * C];      // 100 MB fp16 copy of inputs
__device__ float g_ctx[B * C];
__device__ float g_h[B * H];
__device__ float g_hp[B * H];                     // h @ w_h2h^T + b_h2h, for NEXT att step
__device__ float g_WT_i2h[C * H];                 // [c][h]
__device__ float g_WT_h2h[H * H];                 // [k][h]
__device__ float g_WT_ih[KX * J3H];               // [k][j]
__device__ float g_WT_hh[(H + 8) * J3H];          // [k][j], +8 rows pad for prefetch pipeline
__device__ float g_WT_gen[H * NC];                // [h][nc]
__device__ int   g_is64;

// ---------------- fast math helpers ----------------
__device__ __forceinline__ float tanh_mufu(float x) {   // att energy only (~5e-4 abs err)
    float y; asm("tanh.approx.f32 %0, %1;" : "=f"(y) : "f"(x)); return y;
}
__device__ __forceinline__ float tanh_fast(float x) {   // GRU recurrence (precise path)
    x = fminf(fmaxf(x, -10.f), 10.f);
    float e = __expf(2.f * x);
    return __fdividef(e - 1.f, e + 1.f);
}
__device__ __forceinline__ float sigmoid_fast(float x) {
    return __fdividef(1.f, 1.f + __expf(-x));
}

// ---------------- prep: transposes + h/hp init + targets dtype probe ----------------
__global__ void prep_kernel(const float* __restrict__ w_i2h,
                            const float* __restrict__ w_h2h,
                            const float* __restrict__ b_h2h,
                            const float* __restrict__ w_ih,
                            const float* __restrict__ w_hh,
                            const float* __restrict__ w_gen,
                            const void*  __restrict__ targets_raw) {
    int i0 = blockIdx.x * blockDim.x + threadIdx.x;
    int stride = gridDim.x * blockDim.x;
    for (int i = i0; i < H * C; i += stride) { int h = i / C, c = i % C; g_WT_i2h[c * H + h] = w_i2h[i]; }
    for (int i = i0; i < H * H; i += stride) { int h = i / H, k = i % H; g_WT_h2h[k * H + h] = w_h2h[i]; }
    for (int i = i0; i < J3H * KX; i += stride) { int j = i / KX, k = i % KX; g_WT_ih[k * J3H + j] = w_ih[i]; }
    for (int i = i0; i < J3H * H; i += stride) { int j = i / H, k = i % H; g_WT_hh[k * J3H + j] = w_hh[i]; }
    for (int i = i0; i < NC * H; i += stride) { int n = i / H, h = i % H; g_WT_gen[h * NC + n] = w_gen[i]; }
    for (int i = i0; i < B * H; i += stride) { g_h[i] = 0.f; g_hp[i] = b_h2h[i % H]; }
    if (i0 == 0) {
        // Detect int64 vs int32 targets: valid int64 class indices are all in [0, NC).
        const long long* t64 = (const long long*)targets_raw;
        int ok = 1;
        for (int q = 0; q < 64; q++) {
            long long v = t64[q];
            if (v < 0 || v >= NC) { ok = 0; break; }
        }
        g_is64 = ok;
    }
}

// ---------------- Hproj = inputs @ w_i2h^T ([B*T, H], fp16 out) + fp16 inputs copy ----------------
#define HP_ROWS 64
#define HP_CK   64
__global__ void __launch_bounds__(256) hproj_kernel(const float* __restrict__ inputs) {
    __shared__ __align__(16) float in_s[HP_ROWS][HP_CK];
    __shared__ __align__(16) float wt_s[HP_CK][H];
    int tid = threadIdx.x;
    int tx = tid & 31, ty = tid >> 5;
    int rowbase = blockIdx.x * HP_ROWS;

    float acc[8][3];
#pragma unroll
    for (int r = 0; r < 8; r++)
#pragma unroll
        for (int k = 0; k < 3; k++) acc[r][k] = 0.f;

    for (int c0 = 0; c0 < C; c0 += HP_CK) {
        const float4* wsrc = (const float4*)(g_WT_i2h + c0 * H);
        for (int idx = tid; idx < HP_CK * H / 4; idx += 256)
            ((float4*)wt_s)[idx] = wsrc[idx];
        for (int idx = tid; idx < HP_ROWS * HP_CK / 4; idx += 256) {
            int r = idx >> 4;   // 16 float4 per row
            int q = idx & 15;
            size_t gidx = (size_t)(rowbase + r) * C + c0 + q * 4;
            float4 v = *(const float4*)(inputs + gidx);
            *(float4*)&in_s[r][q * 4] = v;
            // fused fp16 conversion of inputs (gidx divisible by 4)
            ((__half2*)g_in_h)[gidx / 2]     = __floats2half2_rn(v.x, v.y);
            ((__half2*)g_in_h)[gidx / 2 + 1] = __floats2half2_rn(v.z, v.w);
        }
        __syncthreads();
#pragma unroll 2
        for (int cc = 0; cc < HP_CK; ++cc) {
            float w0 = wt_s[cc][tx * 3 + 0];
            float w1 = wt_s[cc][tx * 3 + 1];
            float w2 = wt_s[cc][tx * 3 + 2];
#pragma unroll
            for (int r = 0; r < 8; r++) {
                float iv = in_s[ty * 8 + r][cc];
                acc[r][0] += iv * w0;
                acc[r][1] += iv * w1;
                acc[r][2] += iv * w2;
            }
        }
        __syncthreads();
    }
#pragma unroll
    for (int r = 0; r < 8; r++) {
        __half* dst = g_Hproj_h + (size_t)(rowbase + ty * 8 + r) * H + tx * 3;
        dst[0] = __float2half_rn(acc[r][0]);
        dst[1] = __float2half_rn(acc[r][1]);
        dst[2] = __float2half_rn(acc[r][2]);
    }
}

// ---------------- per-step attention: context[b] from precomputed hp[b] ----------------
__global__ void __launch_bounds__(256) att_kernel(const float* __restrict__ w_score) {
    __shared__ float hp_s[H], sv_s[H];
    __shared__ float e_s[T], alpha_s[T], red[T];
    int tid = threadIdx.x;
    int b = blockIdx.x;

    if (tid < H) { hp_s[tid] = g_hp[b * H + tid]; sv_s[tid] = w_score[tid]; }
    __syncthreads();

    // e[t] = sum_h sv[h] * tanh(Hproj[b,t,h] + hp[h]); warp-per-t, lanes along h (fp16 loads)
    int w = tid >> 5, l = tid & 31;
    const __half2* hb2 = (const __half2*)(g_Hproj_h + (size_t)b * T * H);
#pragma unroll 2
    for (int i = 0; i < 16; i++) {
        int t = w * 16 + i;
        const __half2* row = hb2 + t * (H / 2);
        float2 fa = __half22float2(row[l]);
        float v = sv_s[2 * l]     * tanh_mufu(fa.x + hp_s[2 * l])
                + sv_s[2 * l + 1] * tanh_mufu(fa.y + hp_s[2 * l + 1]);
        if (l < 16) {
            float2 fb = __half22float2(row[32 + l]);
            v += sv_s[64 + 2 * l] * tanh_mufu(fb.x + hp_s[64 + 2 * l])
               + sv_s[65 + 2 * l] * tanh_mufu(fb.y + hp_s[65 + 2 * l]);
        }
#pragma unroll
        for (int off = 16; off > 0; off >>= 1) v += __shfl_xor_sync(0xffffffffu, v, off);
        if (l == 0) e_s[t] = v;
    }
    __syncthreads();

    // softmax over T=128
    if (tid < T) red[tid] = e_s[tid];
    __syncthreads();
    for (int off = 64; off > 0; off >>= 1) {
        if (tid < off) red[tid] = fmaxf(red[tid], red[tid + off]);
        __syncthreads();
    }
    float mx = red[0];
    __syncthreads();
    if (tid < T) { float p = __expf(e_s[tid] - mx); alpha_s[tid] = p; red[tid] = p; }
    __syncthreads();
    for (int off = 64; off > 0; off >>= 1) {
        if (tid < off) red[tid] += red[tid + off];
        __syncthreads();
    }
    float inv = __fdividef(1.f, red[0]);
    __syncthreads();
    if (tid < T) alpha_s[tid] *= inv;
    __syncthreads();

    // context[c] = sum_t alpha[t] * inputs[b,t,c]  (fp16 inputs, half2 per thread)
    if (tid < C / 2) {
        const __half2* ip = (const __half2*)g_in_h + (size_t)b * T * (C / 2) + tid;
        float ax = 0.f, ay = 0.f;
#pragma unroll 4
        for (int t = 0; t < T; t++) {
            float2 f = __half22float2(ip[t * (C / 2)]);
            float al = alpha_s[t];
            ax += al * f.x; ay += al * f.y;
        }
        g_ctx[b * C + 2 * tid]     = ax;
        g_ctx[b * C + 2 * tid + 1] = ay;
    }
}

// ---------------- per-step GRU + generator + next-step hp, 8 batch items per block ----------------
#define FMA8(ACC, WV, PTR) do {                                           \
    const float4* _p = (const float4*)(PTR);                              \
    float4 _a = _p[0], _b = _p[1];                                        \
    ACC[0] += (WV) * _a.x; ACC[1] += (WV) * _a.y;                         \
    ACC[2] += (WV) * _a.z; ACC[3] += (WV) * _a.w;                         \
    ACC[4] += (WV) * _b.x; ACC[5] += (WV) * _b.y;                         \
    ACC[6] += (WV) * _b.z; ACC[7] += (WV) * _b.w;                         \
} while (0)

__global__ void __launch_bounds__(288) gru_kernel(const void* __restrict__ targets_raw,
                                                  const float* __restrict__ b_ih,
                                                  const float* __restrict__ b_hh,
                                                  const float* __restrict__ b_h2h,
                                                  const float* __restrict__ b_gen,
                                                  float* __restrict__ probs, int s) {
    __shared__ __align__(16) float xsT[C][GB];     // context, transposed
    __shared__ __align__(16) float hsT[H][GB];     // h (then h_new), transposed
    __shared__ float Ssum[GB][2 * H];              // gi+gh for r,z gates
    __shared__ float INs[GB][H];                   // i_n
    __shared__ float HNs[GB][H];                   // h_n (gh part)
    __shared__ int cls_s[GB];

    int tid = threadIdx.x;
    int b0 = blockIdx.x * GB;

    for (int idx = tid; idx < GB * C; idx += J3H) { int bb = idx / C, k = idx % C; xsT[k][bb] = g_ctx[(b0 + bb) * C + k]; }
    for (int idx = tid; idx < GB * H; idx += J3H) { int bb = idx / H, k = idx % H; hsT[k][bb] = g_h[(b0 + bb) * H + k]; }
    if (tid < GB) {
        int cls;
        if (g_is64) cls = (int)((const long long*)targets_raw)[(size_t)(b0 + tid) * S + s];
        else        cls = ((const int*)targets_raw)[(size_t)(b0 + tid) * S + s];
        cls_s[tid] = cls;
    }
    __syncthreads();

    int j = tid;  // 0..287
    float accI[GB], accH[GB];
    float bI = b_ih[j], bH = b_hh[j];
#pragma unroll
    for (int bb = 0; bb < GB; bb++) accI[bb] = bI + g_WT_ih[(C + cls_s[bb]) * J3H + j];  // one-hot column
#pragma unroll
    for (int bb = 0; bb < GB; bb++) accH[bb] = bH;

    // input GEMM: cross-iteration register double-buffer (latency fully hidden)
    {
        const float* Wp = g_WT_ih + j;
        float w[8];
#pragma unroll
        for (int u = 0; u < 8; u++) w[u] = Wp[u * J3H];
#pragma unroll 1
        for (int k0 = 0; k0 < C; k0 += 8) {
            float wn[8];
            // prefetch next tile; k0+8+u <= 199 < KX=230 -> always in-bounds
#pragma unroll
            for (int u = 0; u < 8; u++) wn[u] = Wp[(k0 + 8 + u) * J3H];
#pragma unroll
            for (int u = 0; u < 8; u++) FMA8(accI, w[u], &xsT[k0 + u][0]);
#pragma unroll
            for (int u = 0; u < 8; u++) w[u] = wn[u];
        }
    }
    // hidden GEMM: same pipeline; g_WT_hh padded to H+8 rows so prefetch stays in-bounds
    {
        const float* Wp = g_WT_hh + j;
        float w[8];
#pragma unroll
        for (int u = 0; u < 8; u++) w[u] = Wp[u * J3H];
#pragma unroll 1
        for (int k0 = 0; k0 < H; k0 += 8) {
            float wn[8];
#pragma unroll
            for (int u = 0; u < 8; u++) wn[u] = Wp[(k0 + 8 + u) * J3H];
#pragma unroll
            for (int u = 0; u < 8; u++) FMA8(accH, w[u], &hsT[k0 + u][0]);
#pragma unroll
            for (int u = 0; u < 8; u++) w[u] = wn[u];
        }
    }

    if (j < 2 * H) {
#pragma unroll
        for (int bb = 0; bb < GB; bb++) Ssum[bb][j] = accI[bb] + accH[bb];
    } else {
        int jj = j - 2 * H;
#pragma unroll
        for (int bb = 0; bb < GB; bb++) { INs[bb][jj] = accI[bb]; HNs[bb][jj] = accH[bb]; }
    }
    __syncthreads();

    // gates + h update
    for (int idx = tid; idx < GB * H; idx += J3H) {
        int bb = idx / H, h = idx % H;
        float r = sigmoid_fast(Ssum[bb][h]);
        float z = sigmoid_fast(Ssum[bb][H + h]);
        float n = tanh_fast(INs[bb][h] + r * HNs[bb][h]);
        float hn = (1.f - z) * n + z * hsT[h][bb];
        g_h[(b0 + bb) * H + h] = hn;
        hsT[h][bb] = hn;   // own slot: read-then-write, race-free
    }
    __syncthreads();

    // generator: probs[b,s,:] = h_new @ w_gen^T + b_gen
    for (int idx = tid; idx < GB * NC; idx += J3H) {
        int bb = idx / NC, nc = idx % NC;
        float acc = b_gen[nc];
#pragma unroll 4
        for (int h = 0; h < H; h++) acc += g_WT_gen[h * NC + nc] * hsT[h][bb];
        probs[(size_t)((b0 + bb) * S + s) * NC + nc] = acc;
    }

    // next-step hp: hp[b] = h_new @ w_h2h^T + b_h2h  (hoisted out of att)
    for (int idx = tid; idx < GB * H; idx += J3H) {
        int bb = idx / H, h = idx % H;
        float acc = b_h2h[h];
#pragma unroll 4
        for (int k = 0; k < H; k++) acc += g_WT_h2h[k * H + h] * hsT[k][bb];
        g_hp[(b0 + bb) * H + h] = acc;
    }
}

// ---------------- launch ----------------
extern "C" void kernel_launch(void* const* d_in, const int* in_sizes, int n_in,
                              void* d_out, int out_size) {
    const float* inputs  = (const float*)d_in[0];
    const void*  targets = d_in[1];
    const float* w_i2h   = (const float*)d_in[2];
    const float* w_h2h   = (const float*)d_in[3];
    const float* b_h2h   = (const float*)d_in[4];
    const float* w_score = (const float*)d_in[5];
    const float* w_ih    = (const float*)d_in[6];
    const float* w_hh    = (const float*)d_in[7];
    const float* b_ih    = (const float*)d_in[8];
    const float* b_hh    = (const float*)d_in[9];
    const float* w_gen   = (const float*)d_in[10];
    const float* b_gen   = (const float*)d_in[11];
    float* probs = (float*)d_out;

    prep_kernel<<<148, 256>>>(w_i2h, w_h2h, b_h2h, w_ih, w_hh, w_gen, targets);
    hproj_kernel<<<(B * T) / HP_ROWS, 256>>>(inputs);
    for (int s = 0; s < S; s++) {
        att_kernel<<<B, 256>>>(w_score);
        gru_kernel<<<B / GB, J3H>>>(targets, b_ih, b_hh, b_h2h, b_gen, probs, s);
    }
}

// round 10
// speedup vs baseline: 1.9019x; 1.3082x over previous
#include <cuda_runtime.h>
#include <cuda_fp16.h>
#include <cstdint>

#define B 2048
#define T 128
#define C 192
#define H 96
#define NC 38
#define S 25
#define J3H 288        // 3*H
#define KX 230         // C + NC
#define GB 4           // batch items per GRU block

// ---------------- device scratch (no allocations allowed) ----------------
__device__ __half g_Hproj_h[(size_t)B * T * H];   // 50 MB fp16
__device__ __half g_in_h[(size_t)B * T * C];      // 100 MB fp16 copy of inputs
__device__ float g_ctx[B * C];
__device__ float g_h[B * H];
__device__ float g_hp[B * H];                     // h @ w_h2h^T + b_h2h, for NEXT att step
__device__ float g_WT_i2h[C * H];                 // [c][h]
__device__ float g_WT_h2h[H * H];                 // [k][h]
__device__ float g_WT_ih[KX * J3H];               // [k][j]
__device__ float g_WT_hh[(H + 8) * J3H];          // [k][j], +8 rows pad for prefetch pipeline
__device__ float g_WT_gen[H * NC];                // [h][nc]
__device__ int   g_is64;

// ---------------- packed fp32x2 helpers (Blackwell) ----------------
__device__ __forceinline__ unsigned long long pack2(float lo, float hi) {
    unsigned long long r;
    asm("mov.b64 %0, {%1, %2};" : "=l"(r) : "f"(lo), "f"(hi));
    return r;
}
__device__ __forceinline__ float2 unpack2(unsigned long long v) {
    float lo, hi;
    asm("mov.b64 {%0, %1}, %2;" : "=f"(lo), "=f"(hi) : "l"(v));
    return make_float2(lo, hi);
}
__device__ __forceinline__ void fmaX2(unsigned long long& d, unsigned long long a, unsigned long long b) {
    asm("fma.rn.f32x2 %0, %1, %2, %0;" : "+l"(d) : "l"(a), "l"(b));
}

// ---------------- fast math helpers ----------------
__device__ __forceinline__ float tanh_mufu(float x) {   // att energy only (~5e-4 abs err)
    float y; asm("tanh.approx.f32 %0, %1;" : "=f"(y) : "f"(x)); return y;
}
__device__ __forceinline__ float tanh_fast(float x) {   // GRU recurrence (precise path)
    x = fminf(fmaxf(x, -10.f), 10.f);
    float e = __expf(2.f * x);
    return __fdividef(e - 1.f, e + 1.f);
}
__device__ __forceinline__ float sigmoid_fast(float x) {
    return __fdividef(1.f, 1.f + __expf(-x));
}

// ---------------- prep: transposes + h/hp init + targets dtype probe ----------------
__global__ void prep_kernel(const float* __restrict__ w_i2h,
                            const float* __restrict__ w_h2h,
                            const float* __restrict__ b_h2h,
                            const float* __restrict__ w_ih,
                            const float* __restrict__ w_hh,
                            const float* __restrict__ w_gen,
                            const void*  __restrict__ targets_raw) {
    int i0 = blockIdx.x * blockDim.x + threadIdx.x;
    int stride = gridDim.x * blockDim.x;
    for (int i = i0; i < H * C; i += stride) { int h = i / C, c = i % C; g_WT_i2h[c * H + h] = w_i2h[i]; }
    for (int i = i0; i < H * H; i += stride) { int h = i / H, k = i % H; g_WT_h2h[k * H + h] = w_h2h[i]; }
    for (int i = i0; i < J3H * KX; i += stride) { int j = i / KX, k = i % KX; g_WT_ih[k * J3H + j] = w_ih[i]; }
    for (int i = i0; i < J3H * H; i += stride) { int j = i / H, k = i % H; g_WT_hh[k * J3H + j] = w_hh[i]; }
    for (int i = i0; i < NC * H; i += stride) { int n = i / H, h = i % H; g_WT_gen[h * NC + n] = w_gen[i]; }
    for (int i = i0; i < B * H; i += stride) { g_h[i] = 0.f; g_hp[i] = b_h2h[i % H]; }
    if (i0 == 0) {
        // Detect int64 vs int32 targets: valid int64 class indices are all in [0, NC).
        const long long* t64 = (const long long*)targets_raw;
        int ok = 1;
        for (int q = 0; q < 64; q++) {
            long long v = t64[q];
            if (v < 0 || v >= NC) { ok = 0; break; }
        }
        g_is64 = ok;
    }
}

// ---------------- Hproj = inputs @ w_i2h^T ([B*T, H], fp16 out) + fp16 inputs copy ----------------
// f32x2 packed math: row-pairs packed along the M dimension (bit-exact fp32 per row).
#define HP_ROWS 64
#define HP_CK   64
__global__ void __launch_bounds__(256) hproj_kernel(const float* __restrict__ inputs) {
    __shared__ __align__(16) float in_sT[HP_CK][HP_ROWS];   // [cc][r] transposed tile
    __shared__ __align__(16) float wt_s[HP_CK][H];
    int tid = threadIdx.x;
    int tx = tid & 31, ty = tid >> 5;
    int rowbase = blockIdx.x * HP_ROWS;

    unsigned long long accp[4][3];   // 4 row-pairs x 3 h-columns, packed (row2rp, row2rp+1)
#pragma unroll
    for (int rp = 0; rp < 4; rp++)
#pragma unroll
        for (int k = 0; k < 3; k++) accp[rp][k] = pack2(0.f, 0.f);

    for (int c0 = 0; c0 < C; c0 += HP_CK) {
        const float4* wsrc = (const float4*)(g_WT_i2h + c0 * H);
        for (int idx = tid; idx < HP_CK * H / 4; idx += 256)
            ((float4*)wt_s)[idx] = wsrc[idx];
        for (int idx = tid; idx < HP_ROWS * HP_CK / 4; idx += 256) {
            int r = idx >> 4;   // 16 float4 per row
            int q = idx & 15;
            size_t gidx = (size_t)(rowbase + r) * C + c0 + q * 4;
            float4 v = *(const float4*)(inputs + gidx);
            in_sT[q * 4 + 0][r] = v.x;
            in_sT[q * 4 + 1][r] = v.y;
            in_sT[q * 4 + 2][r] = v.z;
            in_sT[q * 4 + 3][r] = v.w;
            // fused fp16 conversion of inputs (gidx divisible by 4)
            ((__half2*)g_in_h)[gidx / 2]     = __floats2half2_rn(v.x, v.y);
            ((__half2*)g_in_h)[gidx / 2 + 1] = __floats2half2_rn(v.z, v.w);
        }
        __syncthreads();
#pragma unroll 2
        for (int cc = 0; cc < HP_CK; ++cc) {
            unsigned long long W0 = pack2(wt_s[cc][tx * 3 + 0], wt_s[cc][tx * 3 + 0]);
            unsigned long long W1 = pack2(wt_s[cc][tx * 3 + 1], wt_s[cc][tx * 3 + 1]);
            unsigned long long W2 = pack2(wt_s[cc][tx * 3 + 2], wt_s[cc][tx * 3 + 2]);
            const ulonglong2* ivp = (const ulonglong2*)&in_sT[cc][ty * 8];  // 8 rows = 2x16B
            ulonglong2 iva = ivp[0], ivb = ivp[1];
            fmaX2(accp[0][0], iva.x, W0); fmaX2(accp[0][1], iva.x, W1); fmaX2(accp[0][2], iva.x, W2);
            fmaX2(accp[1][0], iva.y, W0); fmaX2(accp[1][1], iva.y, W1); fmaX2(accp[1][2], iva.y, W2);
            fmaX2(accp[2][0], ivb.x, W0); fmaX2(accp[2][1], ivb.x, W1); fmaX2(accp[2][2], ivb.x, W2);
            fmaX2(accp[3][0], ivb.y, W0); fmaX2(accp[3][1], ivb.y, W1); fmaX2(accp[3][2], ivb.y, W2);
        }
        __syncthreads();
    }
#pragma unroll
    for (int rp = 0; rp < 4; rp++) {
        float2 a0 = unpack2(accp[rp][0]);
        float2 a1 = unpack2(accp[rp][1]);
        float2 a2 = unpack2(accp[rp][2]);
        __half* d0 = g_Hproj_h + (size_t)(rowbase + ty * 8 + 2 * rp) * H + tx * 3;
        __half* d1 = d0 + H;
        d0[0] = __float2half_rn(a0.x); d0[1] = __float2half_rn(a1.x); d0[2] = __float2half_rn(a2.x);
        d1[0] = __float2half_rn(a0.y); d1[1] = __float2half_rn(a1.y); d1[2] = __float2half_rn(a2.y);
    }
}

// ---------------- per-step attention: context[b] from precomputed hp[b] ----------------
__global__ void __launch_bounds__(256) att_kernel(const float* __restrict__ w_score) {
    __shared__ float hp_s[H], sv_s[H];
    __shared__ float e_s[T], alpha_s[T];
    int tid = threadIdx.x;
    int b = blockIdx.x;

    if (tid < H) { hp_s[tid] = g_hp[b * H + tid]; sv_s[tid] = w_score[tid]; }
    __syncthreads();

    // e[t] = sum_h sv[h] * tanh(Hproj[b,t,h] + hp[h]); warp-per-t, lanes along h (fp16 loads)
    int w = tid >> 5, l = tid & 31;
    const __half2* hb2 = (const __half2*)(g_Hproj_h + (size_t)b * T * H);
#pragma unroll 2
    for (int i = 0; i < 16; i++) {
        int t = w * 16 + i;
        const __half2* row = hb2 + t * (H / 2);
        float2 fa = __half22float2(row[l]);
        float v = sv_s[2 * l]     * tanh_mufu(fa.x + hp_s[2 * l])
                + sv_s[2 * l + 1] * tanh_mufu(fa.y + hp_s[2 * l + 1]);
        if (l < 16) {
            float2 fb = __half22float2(row[32 + l]);
            v += sv_s[64 + 2 * l] * tanh_mufu(fb.x + hp_s[64 + 2 * l])
               + sv_s[65 + 2 * l] * tanh_mufu(fb.y + hp_s[65 + 2 * l]);
        }
#pragma unroll
        for (int off = 16; off > 0; off >>= 1) v += __shfl_xor_sync(0xffffffffu, v, off);
        if (l == 0) e_s[t] = v;
    }
    __syncthreads();

    // softmax over T=128: single warp, shfl reductions (2 barriers total)
    if (tid < 32) {
        float e0 = e_s[tid], e1 = e_s[tid + 32], e2 = e_s[tid + 64], e3 = e_s[tid + 96];
        float m = fmaxf(fmaxf(e0, e1), fmaxf(e2, e3));
#pragma unroll
        for (int off = 16; off > 0; off >>= 1) m = fmaxf(m, __shfl_xor_sync(0xffffffffu, m, off));
        float p0 = __expf(e0 - m), p1 = __expf(e1 - m), p2 = __expf(e2 - m), p3 = __expf(e3 - m);
        float ssum = p0 + p1 + p2 + p3;
#pragma unroll
        for (int off = 16; off > 0; off >>= 1) ssum += __shfl_xor_sync(0xffffffffu, ssum, off);
        float inv = __fdividef(1.f, ssum);
        alpha_s[tid]      = p0 * inv;
        alpha_s[tid + 32] = p1 * inv;
        alpha_s[tid + 64] = p2 * inv;
        alpha_s[tid + 96] = p3 * inv;
    }
    __syncthreads();

    // context[c] = sum_t alpha[t] * inputs[b,t,c]  (fp16 inputs, half2 per thread)
    if (tid < C / 2) {
        const __half2* ip = (const __half2*)g_in_h + (size_t)b * T * (C / 2) + tid;
        float ax = 0.f, ay = 0.f;
#pragma unroll 8
        for (int t = 0; t < T; t++) {
            float2 f = __half22float2(ip[t * (C / 2)]);
            float al = alpha_s[t];
            ax += al * f.x; ay += al * f.y;
        }
        g_ctx[b * C + 2 * tid]     = ax;
        g_ctx[b * C + 2 * tid + 1] = ay;
    }
}

// ---------------- per-step GRU + generator + next-step hp, 4 batch items per block ----------------
// f32x2 packed accumulators: (bb0,bb1) and (bb2,bb3)
#define FMA4X2(ACC2, WV2, PTR) do {                                       \
    ulonglong2 _v = *(const ulonglong2*)(PTR);                            \
    fmaX2(ACC2[0], _v.x, WV2);                                            \
    fmaX2(ACC2[1], _v.y, WV2);                                            \
} while (0)

__global__ void __launch_bounds__(288) gru_kernel(const void* __restrict__ targets_raw,
                                                  const float* __restrict__ b_ih,
                                                  const float* __restrict__ b_hh,
                                                  const float* __restrict__ b_h2h,
                                                  const float* __restrict__ b_gen,
                                                  float* __restrict__ probs, int s) {
    __shared__ __align__(16) float xsT[C][GB];     // context, transposed (16B rows)
    __shared__ __align__(16) float hsT[H][GB];     // h (then h_new), transposed
    __shared__ float Ssum[GB][2 * H];              // gi+gh for r,z gates
    __shared__ float INs[GB][H];                   // i_n
    __shared__ float HNs[GB][H];                   // h_n (gh part)
    __shared__ int cls_s[GB];

    int tid = threadIdx.x;
    int b0 = blockIdx.x * GB;

    for (int idx = tid; idx < GB * C; idx += J3H) { int bb = idx / C, k = idx % C; xsT[k][bb] = g_ctx[(b0 + bb) * C + k]; }
    for (int idx = tid; idx < GB * H; idx += J3H) { int bb = idx / H, k = idx % H; hsT[k][bb] = g_h[(b0 + bb) * H + k]; }
    if (tid < GB) {
        int cls;
        if (g_is64) cls = (int)((const long long*)targets_raw)[(size_t)(b0 + tid) * S + s];
        else        cls = ((const int*)targets_raw)[(size_t)(b0 + tid) * S + s];
        cls_s[tid] = cls;
    }
    __syncthreads();

    int j = tid;  // 0..287
    float bI = b_ih[j], bH = b_hh[j];
    float aI[GB];
#pragma unroll
    for (int bb = 0; bb < GB; bb++) aI[bb] = bI + g_WT_ih[(C + cls_s[bb]) * J3H + j];  // one-hot column
    unsigned long long accI2[2] = { pack2(aI[0], aI[1]), pack2(aI[2], aI[3]) };
    unsigned long long accH2[2] = { pack2(bH, bH), pack2(bH, bH) };

    // input GEMM: cross-iteration register double-buffer + f32x2
    {
        const float* Wp = g_WT_ih + j;
        float w[8];
#pragma unroll
        for (int u = 0; u < 8; u++) w[u] = Wp[u * J3H];
#pragma unroll 1
        for (int k0 = 0; k0 < C; k0 += 8) {
            float wn[8];
            // prefetch next tile; k0+8+u <= 199 < KX=230 -> always in-bounds
#pragma unroll
            for (int u = 0; u < 8; u++) wn[u] = Wp[(k0 + 8 + u) * J3H];
#pragma unroll
            for (int u = 0; u < 8; u++) {
                unsigned long long W2 = pack2(w[u], w[u]);
                FMA4X2(accI2, W2, &xsT[k0 + u][0]);
            }
#pragma unroll
            for (int u = 0; u < 8; u++) w[u] = wn[u];
        }
    }
    // hidden GEMM: same pipeline; g_WT_hh padded to H+8 rows so prefetch stays in-bounds
    {
        const float* Wp = g_WT_hh + j;
        float w[8];
#pragma unroll
        for (int u = 0; u < 8; u++) w[u] = Wp[u * J3H];
#pragma unroll 1
        for (int k0 = 0; k0 < H; k0 += 8) {
            float wn[8];
#pragma unroll
            for (int u = 0; u < 8; u++) wn[u] = Wp[(k0 + 8 + u) * J3H];
#pragma unroll
            for (int u = 0; u < 8; u++) {
                unsigned long long W2 = pack2(w[u], w[u]);
                FMA4X2(accH2, W2, &hsT[k0 + u][0]);
            }
#pragma unroll
            for (int u = 0; u < 8; u++) w[u] = wn[u];
        }
    }

    {
        float2 i01 = unpack2(accI2[0]), i23 = unpack2(accI2[1]);
        float2 h01 = unpack2(accH2[0]), h23 = unpack2(accH2[1]);
        float accI[GB] = { i01.x, i01.y, i23.x, i23.y };
        float accH[GB] = { h01.x, h01.y, h23.x, h23.y };
        if (j < 2 * H) {
#pragma unroll
            for (int bb = 0; bb < GB; bb++) Ssum[bb][j] = accI[bb] + accH[bb];
        } else {
            int jj = j - 2 * H;
#pragma unroll
            for (int bb = 0; bb < GB; bb++) { INs[bb][jj] = accI[bb]; HNs[bb][jj] = accH[bb]; }
        }
    }
    __syncthreads();

    // gates + h update
    for (int idx = tid; idx < GB * H; idx += J3H) {
        int bb = idx / H, h = idx % H;
        float r = sigmoid_fast(Ssum[bb][h]);
        float z = sigmoid_fast(Ssum[bb][H + h]);
        float n = tanh_fast(INs[bb][h] + r * HNs[bb][h]);
        float hn = (1.f - z) * n + z * hsT[h][bb];
        g_h[(b0 + bb) * H + h] = hn;
        hsT[h][bb] = hn;   // own slot: read-then-write, race-free
    }
    __syncthreads();

    // generator: probs[b,s,:] = h_new @ w_gen^T + b_gen
    for (int idx = tid; idx < GB * NC; idx += J3H) {
        int bb = idx / NC, nc = idx % NC;
        float acc = b_gen[nc];
#pragma unroll 4
        for (int h = 0; h < H; h++) acc += g_WT_gen[h * NC + nc] * hsT[h][bb];
        probs[(size_t)((b0 + bb) * S + s) * NC + nc] = acc;
    }

    // next-step hp: hp[b] = h_new @ w_h2h^T + b_h2h  (hoisted out of att)
    for (int idx = tid; idx < GB * H; idx += J3H) {
        int bb = idx / H, h = idx % H;
        float acc = b_h2h[h];
#pragma unroll 4
        for (int k = 0; k < H; k++) acc += g_WT_h2h[k * H + h] * hsT[k][bb];
        g_hp[(b0 + bb) * H + h] = acc;
    }
}

// ---------------- launch ----------------
extern "C" void kernel_launch(void* const* d_in, const int* in_sizes, int n_in,
                              void* d_out, int out_size) {
    const float* inputs  = (const float*)d_in[0];
    const void*  targets = d_in[1];
    const float* w_i2h   = (const float*)d_in[2];
    const float* w_h2h   = (const float*)d_in[3];
    const float* b_h2h   = (const float*)d_in[4];
    const float* w_score = (const float*)d_in[5];
    const float* w_ih    = (const float*)d_in[6];
    const float* w_hh    = (const float*)d_in[7];
    const float* b_ih    = (const float*)d_in[8];
    const float* b_hh    = (const float*)d_in[9];
    const float* w_gen   = (const float*)d_in[10];
    const float* b_gen   = (const float*)d_in[11];
    float* probs = (float*)d_out;

    prep_kernel<<<148, 256>>>(w_i2h, w_h2h, b_h2h, w_ih, w_hh, w_gen, targets);
    hproj_kernel<<<(B * T) / HP_ROWS, 256>>>(inputs);
    for (int s = 0; s < S; s++) {
        att_kernel<<<B, 256>>>(w_score);
        gru_kernel<<<B / GB, J3H>>>(targets, b_ih, b_hh, b_h2h, b_gen, probs, s);
    }
}

// round 11
// speedup vs baseline: 2.1495x; 1.1302x over previous
#include <cuda_runtime.h>
#include <cuda_fp16.h>
#include <cstdint>

#define B 2048
#define T 128
#define C 192
#define H 96
#define NC 38
#define S 25
#define J3H 288        // 3*H
#define KX 230         // C + NC
#define GB 4           // batch items per GRU block

// ---------------- device scratch (no allocations allowed) ----------------
__device__ __half g_Hproj_h[(size_t)B * T * H];   // 50 MB fp16
__device__ __half g_in_h[(size_t)B * T * C];      // 100 MB fp16 copy of inputs
__device__ float g_ctx[B * C];
__device__ float g_h[B * H];
__device__ float g_hp[B * H];                     // h @ w_h2h^T + b_h2h, for NEXT att step
__device__ float g_WT_i2h[C * H];                 // [c][h]
__device__ float g_WT_h2h[H * H];                 // [k][h]
__device__ float g_WT_ih[KX * J3H];               // [k][j] fp32 (one-hot gather only)
__device__ __half2 g_WT_ih_h2[(C / 2 + 4) * J3H]; // [k2][j], pair over k, +4 rows prefetch pad
__device__ __half2 g_WT_hh_h2[(H / 2 + 4) * J3H]; // [k2][j], +4 rows prefetch pad
__device__ float g_WT_gen[H * NC];                // [h][nc]
__device__ int   g_is64;

// ---------------- packed fp32x2 helpers (Blackwell) ----------------
__device__ __forceinline__ unsigned long long pack2(float lo, float hi) {
    unsigned long long r;
    asm("mov.b64 %0, {%1, %2};" : "=l"(r) : "f"(lo), "f"(hi));
    return r;
}
__device__ __forceinline__ float2 unpack2(unsigned long long v) {
    float lo, hi;
    asm("mov.b64 {%0, %1}, %2;" : "=f"(lo), "=f"(hi) : "l"(v));
    return make_float2(lo, hi);
}
__device__ __forceinline__ void fmaX2(unsigned long long& d, unsigned long long a, unsigned long long b) {
    asm("fma.rn.f32x2 %0, %1, %2, %0;" : "+l"(d) : "l"(a), "l"(b));
}

// ---------------- fast math helpers ----------------
__device__ __forceinline__ float tanh_mufu(float x) {   // att energy only (~5e-4 abs err)
    float y; asm("tanh.approx.f32 %0, %1;" : "=f"(y) : "f"(x)); return y;
}
__device__ __forceinline__ float tanh_fast(float x) {   // GRU recurrence (precise path)
    x = fminf(fmaxf(x, -10.f), 10.f);
    float e = __expf(2.f * x);
    return __fdividef(e - 1.f, e + 1.f);
}
__device__ __forceinline__ float sigmoid_fast(float x) {
    return __fdividef(1.f, 1.f + __expf(-x));
}

// ---------------- prep: transposes + h/hp init + targets dtype probe ----------------
__global__ void prep_kernel(const float* __restrict__ w_i2h,
                            const float* __restrict__ w_h2h,
                            const float* __restrict__ b_h2h,
                            const float* __restrict__ w_ih,
                            const float* __restrict__ w_hh,
                            const float* __restrict__ w_gen,
                            const void*  __restrict__ targets_raw) {
    int i0 = blockIdx.x * blockDim.x + threadIdx.x;
    int stride = gridDim.x * blockDim.x;
    for (int i = i0; i < H * C; i += stride) { int h = i / C, c = i % C; g_WT_i2h[c * H + h] = w_i2h[i]; }
    for (int i = i0; i < H * H; i += stride) { int h = i / H, k = i % H; g_WT_h2h[k * H + h] = w_h2h[i]; }
    for (int i = i0; i < J3H * KX; i += stride) { int j = i / KX, k = i % KX; g_WT_ih[k * J3H + j] = w_ih[i]; }
    for (int i = i0; i < (C / 2) * J3H; i += stride) {
        int j = i % J3H, k2 = i / J3H;
        g_WT_ih_h2[k2 * J3H + j] = __floats2half2_rn(w_ih[j * KX + 2 * k2], w_ih[j * KX + 2 * k2 + 1]);
    }
    for (int i = i0; i < (H / 2) * J3H; i += stride) {
        int j = i % J3H, k2 = i / J3H;
        g_WT_hh_h2[k2 * J3H + j] = __floats2half2_rn(w_hh[j * H + 2 * k2], w_hh[j * H + 2 * k2 + 1]);
    }
    // zero the prefetch pads (never used in FMA, but keep deterministic)
    for (int i = i0; i < 4 * J3H; i += stride) {
        g_WT_ih_h2[(C / 2) * J3H + i] = __floats2half2_rn(0.f, 0.f);
        g_WT_hh_h2[(H / 2) * J3H + i] = __floats2half2_rn(0.f, 0.f);
    }
    for (int i = i0; i < NC * H; i += stride) { int n = i / H, h = i % H; g_WT_gen[h * NC + n] = w_gen[i]; }
    for (int i = i0; i < B * H; i += stride) { g_h[i] = 0.f; g_hp[i] = b_h2h[i % H]; }
    if (i0 == 0) {
        // Detect int64 vs int32 targets: valid int64 class indices are all in [0, NC).
        const long long* t64 = (const long long*)targets_raw;
        int ok = 1;
        for (int q = 0; q < 64; q++) {
            long long v = t64[q];
            if (v < 0 || v >= NC) { ok = 0; break; }
        }
        g_is64 = ok;
    }
}

// ---------------- Hproj = inputs @ w_i2h^T ([B*T, H], fp16 out) + fp16 inputs copy ----------------
#define HP_ROWS 64
#define HP_CK   64
__global__ void __launch_bounds__(256) hproj_kernel(const float* __restrict__ inputs) {
    __shared__ __align__(16) float in_sT[HP_CK][HP_ROWS];   // [cc][r] transposed tile
    __shared__ __align__(16) float wt_s[HP_CK][H];
    int tid = threadIdx.x;
    int tx = tid & 31, ty = tid >> 5;
    int rowbase = blockIdx.x * HP_ROWS;

    unsigned long long accp[4][3];   // 4 row-pairs x 3 h-columns, packed
#pragma unroll
    for (int rp = 0; rp < 4; rp++)
#pragma unroll
        for (int k = 0; k < 3; k++) accp[rp][k] = pack2(0.f, 0.f);

    for (int c0 = 0; c0 < C; c0 += HP_CK) {
        const float4* wsrc = (const float4*)(g_WT_i2h + c0 * H);
        for (int idx = tid; idx < HP_CK * H / 4; idx += 256)
            ((float4*)wt_s)[idx] = wsrc[idx];
        for (int idx = tid; idx < HP_ROWS * HP_CK / 4; idx += 256) {
            int r = idx >> 4;   // 16 float4 per row
            int q = idx & 15;
            size_t gidx = (size_t)(rowbase + r) * C + c0 + q * 4;
            float4 v = *(const float4*)(inputs + gidx);
            in_sT[q * 4 + 0][r] = v.x;
            in_sT[q * 4 + 1][r] = v.y;
            in_sT[q * 4 + 2][r] = v.z;
            in_sT[q * 4 + 3][r] = v.w;
            ((__half2*)g_in_h)[gidx / 2]     = __floats2half2_rn(v.x, v.y);
            ((__half2*)g_in_h)[gidx / 2 + 1] = __floats2half2_rn(v.z, v.w);
        }
        __syncthreads();
#pragma unroll 2
        for (int cc = 0; cc < HP_CK; ++cc) {
            unsigned long long W0 = pack2(wt_s[cc][tx * 3 + 0], wt_s[cc][tx * 3 + 0]);
            unsigned long long W1 = pack2(wt_s[cc][tx * 3 + 1], wt_s[cc][tx * 3 + 1]);
            unsigned long long W2 = pack2(wt_s[cc][tx * 3 + 2], wt_s[cc][tx * 3 + 2]);
            const ulonglong2* ivp = (const ulonglong2*)&in_sT[cc][ty * 8];  // 8 rows = 2x16B
            ulonglong2 iva = ivp[0], ivb = ivp[1];
            fmaX2(accp[0][0], iva.x, W0); fmaX2(accp[0][1], iva.x, W1); fmaX2(accp[0][2], iva.x, W2);
            fmaX2(accp[1][0], iva.y, W0); fmaX2(accp[1][1], iva.y, W1); fmaX2(accp[1][2], iva.y, W2);
            fmaX2(accp[2][0], ivb.x, W0); fmaX2(accp[2][1], ivb.x, W1); fmaX2(accp[2][2], ivb.x, W2);
            fmaX2(accp[3][0], ivb.y, W0); fmaX2(accp[3][1], ivb.y, W1); fmaX2(accp[3][2], ivb.y, W2);
        }
        __syncthreads();
    }
#pragma unroll
    for (int rp = 0; rp < 4; rp++) {
        float2 a0 = unpack2(accp[rp][0]);
        float2 a1 = unpack2(accp[rp][1]);
        float2 a2 = unpack2(accp[rp][2]);
        __half* d0 = g_Hproj_h + (size_t)(rowbase + ty * 8 + 2 * rp) * H + tx * 3;
        __half* d1 = d0 + H;
        d0[0] = __float2half_rn(a0.x); d0[1] = __float2half_rn(a1.x); d0[2] = __float2half_rn(a2.x);
        d1[0] = __float2half_rn(a0.y); d1[1] = __float2half_rn(a1.y); d1[2] = __float2half_rn(a2.y);
    }
}

// ---------------- per-step attention: context[b] from precomputed hp[b] ----------------
__global__ void __launch_bounds__(256) att_kernel(const float* __restrict__ w_score) {
    __shared__ float hp_s[H], sv_s[H];
    __shared__ float epart[T][33];           // per-lane energy partials, pad -> conflict-free
    __shared__ float e_s[T], alpha_s[T];
    __shared__ float cpart[2][96][2];        // context t-split partials
    int tid = threadIdx.x;
    int b = blockIdx.x;

    if (tid < H) { hp_s[tid] = g_hp[b * H + tid]; sv_s[tid] = w_score[tid]; }
    __syncthreads();

    // energy partials: warp-per-t, lanes along h; NO shfl chain — store per-lane partial
    int w = tid >> 5, l = tid & 31;
    const __half2* hb2 = (const __half2*)(g_Hproj_h + (size_t)b * T * H);
#pragma unroll 4
    for (int i = 0; i < 16; i++) {
        int t = w * 16 + i;
        const __half2* row = hb2 + t * (H / 2);
        float2 fa = __half22float2(row[l]);
        float v = sv_s[2 * l]     * tanh_mufu(fa.x + hp_s[2 * l])
                + sv_s[2 * l + 1] * tanh_mufu(fa.y + hp_s[2 * l + 1]);
        if (l < 16) {
            float2 fb = __half22float2(row[32 + l]);
            v += sv_s[64 + 2 * l] * tanh_mufu(fb.x + hp_s[64 + 2 * l])
               + sv_s[65 + 2 * l] * tanh_mufu(fb.y + hp_s[65 + 2 * l]);
        }
        epart[t][l] = v;
    }
    __syncthreads();

    // reduce 32 partials per t (conflict-free: stride-33 rows)
    if (tid < T) {
        float s0 = 0.f, s1 = 0.f, s2 = 0.f, s3 = 0.f;
#pragma unroll
        for (int q = 0; q < 32; q += 4) {
            s0 += epart[tid][q];     s1 += epart[tid][q + 1];
            s2 += epart[tid][q + 2]; s3 += epart[tid][q + 3];
        }
        e_s[tid] = (s0 + s1) + (s2 + s3);
    }
    __syncthreads();

    // softmax over T=128: single warp, shfl reductions
    if (tid < 32) {
        float e0 = e_s[tid], e1 = e_s[tid + 32], e2 = e_s[tid + 64], e3 = e_s[tid + 96];
        float m = fmaxf(fmaxf(e0, e1), fmaxf(e2, e3));
#pragma unroll
        for (int off = 16; off > 0; off >>= 1) m = fmaxf(m, __shfl_xor_sync(0xffffffffu, m, off));
        float p0 = __expf(e0 - m), p1 = __expf(e1 - m), p2 = __expf(e2 - m), p3 = __expf(e3 - m);
        float ssum = p0 + p1 + p2 + p3;
#pragma unroll
        for (int off = 16; off > 0; off >>= 1) ssum += __shfl_xor_sync(0xffffffffu, ssum, off);
        float inv = __fdividef(1.f, ssum);
        alpha_s[tid]      = p0 * inv;
        alpha_s[tid + 32] = p1 * inv;
        alpha_s[tid + 64] = p2 * inv;
        alpha_s[tid + 96] = p3 * inv;
    }
    __syncthreads();

    // context[c] = sum_t alpha[t]*inputs[b,t,c]; 2-way t-split, 192 threads active
    if (tid < 192) {
        int col = tid % 96;       // half2 column
        int hf  = tid / 96;       // t-half
        int t0 = hf * 64;
        const __half2* ip = (const __half2*)g_in_h + ((size_t)b * T + t0) * 96 + col;
        float ax = 0.f, ay = 0.f;
#pragma unroll 8
        for (int t = 0; t < 64; t++) {
            float2 f = __half22float2(ip[t * 96]);
            float al = alpha_s[t0 + t];
            ax += al * f.x; ay += al * f.y;
        }
        cpart[hf][col][0] = ax;
        cpart[hf][col][1] = ay;
    }
    __syncthreads();
    if (tid < 96) {
        g_ctx[b * C + 2 * tid]     = cpart[0][tid][0] + cpart[1][tid][0];
        g_ctx[b * C + 2 * tid + 1] = cpart[0][tid][1] + cpart[1][tid][1];
    }
}

// ---------------- per-step GRU + generator + next-step hp, 4 batch items per block ----------------
#define FMA4X2(ACC2, WV2, PTR) do {                                       \
    ulonglong2 _v = *(const ulonglong2*)(PTR);                            \
    fmaX2(ACC2[0], _v.x, WV2);                                            \
    fmaX2(ACC2[1], _v.y, WV2);                                            \
} while (0)

__global__ void __launch_bounds__(288) gru_kernel(const void* __restrict__ targets_raw,
                                                  const float* __restrict__ b_ih,
                                                  const float* __restrict__ b_hh,
                                                  const float* __restrict__ b_h2h,
                                                  const float* __restrict__ b_gen,
                                                  float* __restrict__ probs, int s) {
    __shared__ __align__(16) float xsT[C][GB];     // context, transposed (16B rows)
    __shared__ __align__(16) float hsT[H][GB];     // h (then h_new), transposed
    __shared__ float Ssum[GB][2 * H];              // gi+gh for r,z gates
    __shared__ float INs[GB][H];                   // i_n
    __shared__ float HNs[GB][H];                   // h_n (gh part)
    __shared__ int cls_s[GB];

    int tid = threadIdx.x;
    int b0 = blockIdx.x * GB;

    for (int idx = tid; idx < GB * C; idx += J3H) { int bb = idx / C, k = idx % C; xsT[k][bb] = g_ctx[(b0 + bb) * C + k]; }
    for (int idx = tid; idx < GB * H; idx += J3H) { int bb = idx / H, k = idx % H; hsT[k][bb] = g_h[(b0 + bb) * H + k]; }
    if (tid < GB) {
        int cls;
        if (g_is64) cls = (int)((const long long*)targets_raw)[(size_t)(b0 + tid) * S + s];
        else        cls = ((const int*)targets_raw)[(size_t)(b0 + tid) * S + s];
        cls_s[tid] = cls;
    }
    __syncthreads();

    int j = tid;  // 0..287
    float bI = b_ih[j], bH = b_hh[j];
    float aI[GB];
#pragma unroll
    for (int bb = 0; bb < GB; bb++) aI[bb] = bI + g_WT_ih[(C + cls_s[bb]) * J3H + j];  // one-hot (fp32 copy)
    unsigned long long accI2[2] = { pack2(aI[0], aI[1]), pack2(aI[2], aI[3]) };
    unsigned long long accH2[2] = { pack2(bH, bH), pack2(bH, bH) };

    // input GEMM: fp16 weights (half2 over k), cross-iteration double-buffer, f32x2 accumulate
    {
        const __half2* Wp = g_WT_ih_h2 + j;
        __half2 w[4];
#pragma unroll
        for (int u = 0; u < 4; u++) w[u] = Wp[u * J3H];
#pragma unroll 1
        for (int k0 = 0; k0 < C; k0 += 8) {
            __half2 wn[4];
#pragma unroll
            for (int u = 0; u < 4; u++) wn[u] = Wp[((k0 + 8) / 2 + u) * J3H];  // pad rows keep this in-bounds
#pragma unroll
            for (int u = 0; u < 4; u++) {
                float2 wf = __half22float2(w[u]);
                unsigned long long Wa = pack2(wf.x, wf.x);
                unsigned long long Wb = pack2(wf.y, wf.y);
                FMA4X2(accI2, Wa, &xsT[k0 + 2 * u][0]);
                FMA4X2(accI2, Wb, &xsT[k0 + 2 * u + 1][0]);
            }
#pragma unroll
            for (int u = 0; u < 4; u++) w[u] = wn[u];
        }
    }
    // hidden GEMM: same pipeline
    {
        const __half2* Wp = g_WT_hh_h2 + j;
        __half2 w[4];
#pragma unroll
        for (int u = 0; u < 4; u++) w[u] = Wp[u * J3H];
#pragma unroll 1
        for (int k0 = 0; k0 < H; k0 += 8) {
            __half2 wn[4];
#pragma unroll
            for (int u = 0; u < 4; u++) wn[u] = Wp[((k0 + 8) / 2 + u) * J3H];
#pragma unroll
            for (int u = 0; u < 4; u++) {
                float2 wf = __half22float2(w[u]);
                unsigned long long Wa = pack2(wf.x, wf.x);
                unsigned long long Wb = pack2(wf.y, wf.y);
                FMA4X2(accH2, Wa, &hsT[k0 + 2 * u][0]);
                FMA4X2(accH2, Wb, &hsT[k0 + 2 * u + 1][0]);
            }
#pragma unroll
            for (int u = 0; u < 4; u++) w[u] = wn[u];
        }
    }

    {
        float2 i01 = unpack2(accI2[0]), i23 = unpack2(accI2[1]);
        float2 h01 = unpack2(accH2[0]), h23 = unpack2(accH2[1]);
        float accI[GB] = { i01.x, i01.y, i23.x, i23.y };
        float accH[GB] = { h01.x, h01.y, h23.x, h23.y };
        if (j < 2 * H) {
#pragma unroll
            for (int bb = 0; bb < GB; bb++) Ssum[bb][j] = accI[bb] + accH[bb];
        } else {
            int jj = j - 2 * H;
#pragma unroll
            for (int bb = 0; bb < GB; bb++) { INs[bb][jj] = accI[bb]; HNs[bb][jj] = accH[bb]; }
        }
    }
    __syncthreads();

    // gates + h update
    for (int idx = tid; idx < GB * H; idx += J3H) {
        int bb = idx / H, h = idx % H;
        float r = sigmoid_fast(Ssum[bb][h]);
        float z = sigmoid_fast(Ssum[bb][H + h]);
        float n = tanh_fast(INs[bb][h] + r * HNs[bb][h]);
        float hn = (1.f - z) * n + z * hsT[h][bb];
        g_h[(b0 + bb) * H + h] = hn;
        hsT[h][bb] = hn;   // own slot: read-then-write, race-free
    }
    __syncthreads();

    // generator: probs[b,s,:] = h_new @ w_gen^T + b_gen
    for (int idx = tid; idx < GB * NC; idx += J3H) {
        int bb = idx / NC, nc = idx % NC;
        float acc = b_gen[nc];
#pragma unroll 4
        for (int h = 0; h < H; h++) acc += g_WT_gen[h * NC + nc] * hsT[h][bb];
        probs[(size_t)((b0 + bb) * S + s) * NC + nc] = acc;
    }

    // next-step hp: hp[b] = h_new @ w_h2h^T + b_h2h  (hoisted out of att)
    for (int idx = tid; idx < GB * H; idx += J3H) {
        int bb = idx / H, h = idx % H;
        float acc = b_h2h[h];
#pragma unroll 4
        for (int k = 0; k < H; k++) acc += g_WT_h2h[k * H + h] * hsT[k][bb];
        g_hp[(b0 + bb) * H + h] = acc;
    }
}

// ---------------- launch ----------------
extern "C" void kernel_launch(void* const* d_in, const int* in_sizes, int n_in,
                              void* d_out, int out_size) {
    const float* inputs  = (const float*)d_in[0];
    const void*  targets = d_in[1];
    const float* w_i2h   = (const float*)d_in[2];
    const float* w_h2h   = (const float*)d_in[3];
    const float* b_h2h   = (const float*)d_in[4];
    const float* w_score = (const float*)d_in[5];
    const float* w_ih    = (const float*)d_in[6];
    const float* w_hh    = (const float*)d_in[7];
    const float* b_ih    = (const float*)d_in[8];
    const float* b_hh    = (const float*)d_in[9];
    const float* w_gen   = (const float*)d_in[10];
    const float* b_gen   = (const float*)d_in[11];
    float* probs = (float*)d_out;

    prep_kernel<<<148, 256>>>(w_i2h, w_h2h, b_h2h, w_ih, w_hh, w_gen, targets);
    hproj_kernel<<<(B * T) / HP_ROWS, 256>>>(inputs);
    for (int s = 0; s < S; s++) {
        att_kernel<<<B, 256>>>(w_score);
        gru_kernel<<<B / GB, J3H>>>(targets, b_ih, b_hh, b_h2h, b_gen, probs, s);
    }
}

// round 12
// speedup vs baseline: 2.1755x; 1.0121x over previous
#include <cuda_runtime.h>
#include <cuda_fp16.h>
#include <cstdint>

#define B 2048
#define T 128
#define C 192
#define H 96
#define NC 38
#define S 25
#define J3H 288        // 3*H
#define KX 230         // C + NC
#define GB 2           // batch items per GRU block

// ---------------- device scratch (no allocations allowed) ----------------
__device__ __half g_Hproj_h[(size_t)B * T * H];   // 50 MB fp16
__device__ __half g_in_h[(size_t)B * T * C];      // 100 MB fp16 copy of inputs
__device__ float g_ctx[B * C];
__device__ float g_h[B * H];
__device__ float g_hp[B * H];                     // h @ w_h2h^T + b_h2h, for NEXT att step
__device__ float g_WT_i2h[C * H];                 // [c][h]
__device__ float g_WT_h2h[H * H];                 // [k][h]
__device__ float g_WT_ih[KX * J3H];               // [k][j] fp32 (one-hot gather only)
__device__ __half2 g_WT_ih_h2[(C / 2 + 4) * J3H]; // [k2][j], pair over k, +4 rows prefetch pad
__device__ __half2 g_WT_hh_h2[(H / 2 + 4) * J3H]; // [k2][j], +4 rows prefetch pad
__device__ float g_WT_gen[H * NC];                // [h][nc]
__device__ int   g_is64;

// ---------------- packed fp32x2 helpers (Blackwell) ----------------
__device__ __forceinline__ unsigned long long pack2(float lo, float hi) {
    unsigned long long r;
    asm("mov.b64 %0, {%1, %2};" : "=l"(r) : "f"(lo), "f"(hi));
    return r;
}
__device__ __forceinline__ float2 unpack2(unsigned long long v) {
    float lo, hi;
    asm("mov.b64 {%0, %1}, %2;" : "=f"(lo), "=f"(hi) : "l"(v));
    return make_float2(lo, hi);
}
__device__ __forceinline__ void fmaX2(unsigned long long& d, unsigned long long a, unsigned long long b) {
    asm("fma.rn.f32x2 %0, %1, %2, %0;" : "+l"(d) : "l"(a), "l"(b));
}

// ---------------- fast math helpers ----------------
__device__ __forceinline__ float tanh_mufu(float x) {   // att energy only (~5e-4 abs err)
    float y; asm("tanh.approx.f32 %0, %1;" : "=f"(y) : "f"(x)); return y;
}
__device__ __forceinline__ float tanh_fast(float x) {   // GRU recurrence (precise path)
    x = fminf(fmaxf(x, -10.f), 10.f);
    float e = __expf(2.f * x);
    return __fdividef(e - 1.f, e + 1.f);
}
__device__ __forceinline__ float sigmoid_fast(float x) {
    return __fdividef(1.f, 1.f + __expf(-x));
}

// ---------------- prep: transposes + h/hp init + targets dtype probe ----------------
__global__ void prep_kernel(const float* __restrict__ w_i2h,
                            const float* __restrict__ w_h2h,
                            const float* __restrict__ b_h2h,
                            const float* __restrict__ w_ih,
                            const float* __restrict__ w_hh,
                            const float* __restrict__ w_gen,
                            const void*  __restrict__ targets_raw) {
    int i0 = blockIdx.x * blockDim.x + threadIdx.x;
    int stride = gridDim.x * blockDim.x;
    for (int i = i0; i < H * C; i += stride) { int h = i / C, c = i % C; g_WT_i2h[c * H + h] = w_i2h[i]; }
    for (int i = i0; i < H * H; i += stride) { int h = i / H, k = i % H; g_WT_h2h[k * H + h] = w_h2h[i]; }
    for (int i = i0; i < J3H * KX; i += stride) { int j = i / KX, k = i % KX; g_WT_ih[k * J3H + j] = w_ih[i]; }
    for (int i = i0; i < (C / 2) * J3H; i += stride) {
        int j = i % J3H, k2 = i / J3H;
        g_WT_ih_h2[k2 * J3H + j] = __floats2half2_rn(w_ih[j * KX + 2 * k2], w_ih[j * KX + 2 * k2 + 1]);
    }
    for (int i = i0; i < (H / 2) * J3H; i += stride) {
        int j = i % J3H, k2 = i / J3H;
        g_WT_hh_h2[k2 * J3H + j] = __floats2half2_rn(w_hh[j * H + 2 * k2], w_hh[j * H + 2 * k2 + 1]);
    }
    // zero the prefetch pads (never used in FMA, but keep deterministic)
    for (int i = i0; i < 4 * J3H; i += stride) {
        g_WT_ih_h2[(C / 2) * J3H + i] = __floats2half2_rn(0.f, 0.f);
        g_WT_hh_h2[(H / 2) * J3H + i] = __floats2half2_rn(0.f, 0.f);
    }
    for (int i = i0; i < NC * H; i += stride) { int n = i / H, h = i % H; g_WT_gen[h * NC + n] = w_gen[i]; }
    for (int i = i0; i < B * H; i += stride) { g_h[i] = 0.f; g_hp[i] = b_h2h[i % H]; }
    if (i0 == 0) {
        // Detect int64 vs int32 targets: valid int64 class indices are all in [0, NC).
        const long long* t64 = (const long long*)targets_raw;
        int ok = 1;
        for (int q = 0; q < 64; q++) {
            long long v = t64[q];
            if (v < 0 || v >= NC) { ok = 0; break; }
        }
        g_is64 = ok;
    }
}

// ---------------- Hproj = inputs @ w_i2h^T ([B*T, H], fp16 out) + fp16 inputs copy ----------------
#define HP_ROWS 64
#define HP_CK   64
__global__ void __launch_bounds__(256) hproj_kernel(const float* __restrict__ inputs) {
    __shared__ __align__(16) float in_sT[HP_CK][HP_ROWS];   // [cc][r] transposed tile
    __shared__ __align__(16) float wt_s[HP_CK][H];
    int tid = threadIdx.x;
    int tx = tid & 31, ty = tid >> 5;
    int rowbase = blockIdx.x * HP_ROWS;

    unsigned long long accp[4][3];   // 4 row-pairs x 3 h-columns, packed
#pragma unroll
    for (int rp = 0; rp < 4; rp++)
#pragma unroll
        for (int k = 0; k < 3; k++) accp[rp][k] = pack2(0.f, 0.f);

    for (int c0 = 0; c0 < C; c0 += HP_CK) {
        const float4* wsrc = (const float4*)(g_WT_i2h + c0 * H);
        for (int idx = tid; idx < HP_CK * H / 4; idx += 256)
            ((float4*)wt_s)[idx] = wsrc[idx];
        for (int idx = tid; idx < HP_ROWS * HP_CK / 4; idx += 256) {
            int r = idx >> 4;   // 16 float4 per row
            int q = idx & 15;
            size_t gidx = (size_t)(rowbase + r) * C + c0 + q * 4;
            float4 v = *(const float4*)(inputs + gidx);
            in_sT[q * 4 + 0][r] = v.x;
            in_sT[q * 4 + 1][r] = v.y;
            in_sT[q * 4 + 2][r] = v.z;
            in_sT[q * 4 + 3][r] = v.w;
            ((__half2*)g_in_h)[gidx / 2]     = __floats2half2_rn(v.x, v.y);
            ((__half2*)g_in_h)[gidx / 2 + 1] = __floats2half2_rn(v.z, v.w);
        }
        __syncthreads();
#pragma unroll 2
        for (int cc = 0; cc < HP_CK; ++cc) {
            unsigned long long W0 = pack2(wt_s[cc][tx * 3 + 0], wt_s[cc][tx * 3 + 0]);
            unsigned long long W1 = pack2(wt_s[cc][tx * 3 + 1], wt_s[cc][tx * 3 + 1]);
            unsigned long long W2 = pack2(wt_s[cc][tx * 3 + 2], wt_s[cc][tx * 3 + 2]);
            const ulonglong2* ivp = (const ulonglong2*)&in_sT[cc][ty * 8];  // 8 rows = 2x16B
            ulonglong2 iva = ivp[0], ivb = ivp[1];
            fmaX2(accp[0][0], iva.x, W0); fmaX2(accp[0][1], iva.x, W1); fmaX2(accp[0][2], iva.x, W2);
            fmaX2(accp[1][0], iva.y, W0); fmaX2(accp[1][1], iva.y, W1); fmaX2(accp[1][2], iva.y, W2);
            fmaX2(accp[2][0], ivb.x, W0); fmaX2(accp[2][1], ivb.x, W1); fmaX2(accp[2][2], ivb.x, W2);
            fmaX2(accp[3][0], ivb.y, W0); fmaX2(accp[3][1], ivb.y, W1); fmaX2(accp[3][2], ivb.y, W2);
        }
        __syncthreads();
    }
#pragma unroll
    for (int rp = 0; rp < 4; rp++) {
        float2 a0 = unpack2(accp[rp][0]);
        float2 a1 = unpack2(accp[rp][1]);
        float2 a2 = unpack2(accp[rp][2]);
        __half* d0 = g_Hproj_h + (size_t)(rowbase + ty * 8 + 2 * rp) * H + tx * 3;
        __half* d1 = d0 + H;
        d0[0] = __float2half_rn(a0.x); d0[1] = __float2half_rn(a1.x); d0[2] = __float2half_rn(a2.x);
        d1[0] = __float2half_rn(a0.y); d1[1] = __float2half_rn(a1.y); d1[2] = __float2half_rn(a2.y);
    }
}

// ---------------- per-step attention: context[b] from precomputed hp[b] ----------------
__global__ void __launch_bounds__(256) att_kernel(const float* __restrict__ w_score) {
    __shared__ float hp_s[H], sv_s[H];
    __shared__ float epart[T][33];           // per-lane energy partials, pad -> conflict-free
    __shared__ float e_s[T], alpha_s[T];
    __shared__ float cpart[2][96][2];        // context t-split partials
    int tid = threadIdx.x;
    int b = blockIdx.x;

    if (tid < H) { hp_s[tid] = g_hp[b * H + tid]; sv_s[tid] = w_score[tid]; }
    __syncthreads();

    // energy partials: warp-per-t, lanes along h; store per-lane partial (no shfl chain)
    int w = tid >> 5, l = tid & 31;
    const __half2* hb2 = (const __half2*)(g_Hproj_h + (size_t)b * T * H);
#pragma unroll 4
    for (int i = 0; i < 16; i++) {
        int t = w * 16 + i;
        const __half2* row = hb2 + t * (H / 2);
        float2 fa = __half22float2(row[l]);
        float v = sv_s[2 * l]     * tanh_mufu(fa.x + hp_s[2 * l])
                + sv_s[2 * l + 1] * tanh_mufu(fa.y + hp_s[2 * l + 1]);
        if (l < 16) {
            float2 fb = __half22float2(row[32 + l]);
            v += sv_s[64 + 2 * l] * tanh_mufu(fb.x + hp_s[64 + 2 * l])
               + sv_s[65 + 2 * l] * tanh_mufu(fb.y + hp_s[65 + 2 * l]);
        }
        epart[t][l] = v;
    }
    __syncthreads();

    // reduce 32 partials per t (conflict-free: stride-33 rows)
    if (tid < T) {
        float s0 = 0.f, s1 = 0.f, s2 = 0.f, s3 = 0.f;
#pragma unroll
        for (int q = 0; q < 32; q += 4) {
            s0 += epart[tid][q];     s1 += epart[tid][q + 1];
            s2 += epart[tid][q + 2]; s3 += epart[tid][q + 3];
        }
        e_s[tid] = (s0 + s1) + (s2 + s3);
    }
    __syncthreads();

    // softmax over T=128: single warp, shfl reductions
    if (tid < 32) {
        float e0 = e_s[tid], e1 = e_s[tid + 32], e2 = e_s[tid + 64], e3 = e_s[tid + 96];
        float m = fmaxf(fmaxf(e0, e1), fmaxf(e2, e3));
#pragma unroll
        for (int off = 16; off > 0; off >>= 1) m = fmaxf(m, __shfl_xor_sync(0xffffffffu, m, off));
        float p0 = __expf(e0 - m), p1 = __expf(e1 - m), p2 = __expf(e2 - m), p3 = __expf(e3 - m);
        float ssum = p0 + p1 + p2 + p3;
#pragma unroll
        for (int off = 16; off > 0; off >>= 1) ssum += __shfl_xor_sync(0xffffffffu, ssum, off);
        float inv = __fdividef(1.f, ssum);
        alpha_s[tid]      = p0 * inv;
        alpha_s[tid + 32] = p1 * inv;
        alpha_s[tid + 64] = p2 * inv;
        alpha_s[tid + 96] = p3 * inv;
    }
    __syncthreads();

    // context[c] = sum_t alpha[t]*inputs[b,t,c]; 2-way t-split, 192 threads active
    if (tid < 192) {
        int col = tid % 96;       // half2 column
        int hf  = tid / 96;       // t-half
        int t0 = hf * 64;
        const __half2* ip = (const __half2*)g_in_h + ((size_t)b * T + t0) * 96 + col;
        float ax = 0.f, ay = 0.f;
#pragma unroll 8
        for (int t = 0; t < 64; t++) {
            float2 f = __half22float2(ip[t * 96]);
            float al = alpha_s[t0 + t];
            ax += al * f.x; ay += al * f.y;
        }
        cpart[hf][col][0] = ax;
        cpart[hf][col][1] = ay;
    }
    __syncthreads();
    if (tid < 96) {
        g_ctx[b * C + 2 * tid]     = cpart[0][tid][0] + cpart[1][tid][0];
        g_ctx[b * C + 2 * tid + 1] = cpart[0][tid][1] + cpart[1][tid][1];
    }
}

// ---------------- per-step GRU + generator + next-step hp, 2 batch items per block ----------------
// k-pair-packed activations: xs2[k2] row = {x[2k2][b0], x[2k2][b1], x[2k2+1][b0], x[2k2+1][b1]}
// -> one LDS.128 feeds two k-steps; single packed accumulator (b0,b1) per GEMM.
__global__ void __launch_bounds__(288, 7) gru_kernel(const void* __restrict__ targets_raw,
                                                     const float* __restrict__ b_ih,
                                                     const float* __restrict__ b_hh,
                                                     const float* __restrict__ b_h2h,
                                                     const float* __restrict__ b_gen,
                                                     float* __restrict__ probs, int s) {
    __shared__ __align__(16) float xs2[C / 2][4];    // k-pair-packed context
    __shared__ __align__(16) float hs2[H / 2][4];    // k-pair-packed h (then h_new)
    __shared__ float Ssum[GB][2 * H];                // gi+gh for r,z gates
    __shared__ float INs[GB][H];                     // i_n
    __shared__ float HNs[GB][H];                     // h_n (gh part)
    __shared__ int cls_s[GB];

    int tid = threadIdx.x;
    int b0 = blockIdx.x * GB;

    for (int idx = tid; idx < GB * C; idx += J3H) {
        int bb = idx / C, k = idx % C;
        xs2[k >> 1][(k & 1) * 2 + bb] = g_ctx[(b0 + bb) * C + k];
    }
    for (int idx = tid; idx < GB * H; idx += J3H) {
        int bb = idx / H, k = idx % H;
        hs2[k >> 1][(k & 1) * 2 + bb] = g_h[(b0 + bb) * H + k];
    }
    if (tid < GB) {
        int cls;
        if (g_is64) cls = (int)((const long long*)targets_raw)[(size_t)(b0 + tid) * S + s];
        else        cls = ((const int*)targets_raw)[(size_t)(b0 + tid) * S + s];
        cls_s[tid] = cls;
    }
    __syncthreads();

    int j = tid;  // 0..287
    // init accumulators with bias + one-hot column (fp32 copy)
    unsigned long long accI2 = pack2(b_ih[j] + g_WT_ih[(C + cls_s[0]) * J3H + j],
                                     b_ih[j] + g_WT_ih[(C + cls_s[1]) * J3H + j]);
    float bH = b_hh[j];
    unsigned long long accH2 = pack2(bH, bH);

    // input GEMM: fp16 weight pairs, cross-iteration double-buffer, 1 LDS.128 per 2 k
    {
        const __half2* Wp = g_WT_ih_h2 + j;
        __half2 w[4];
#pragma unroll
        for (int u = 0; u < 4; u++) w[u] = Wp[u * J3H];
#pragma unroll 1
        for (int k2 = 0; k2 < C / 2; k2 += 4) {
            __half2 wn[4];
#pragma unroll
            for (int u = 0; u < 4; u++) wn[u] = Wp[(k2 + 4 + u) * J3H];  // pad rows keep in-bounds
#pragma unroll
            for (int u = 0; u < 4; u++) {
                float2 wf = __half22float2(w[u]);
                ulonglong2 v = *(const ulonglong2*)&xs2[k2 + u][0];
                fmaX2(accI2, v.x, pack2(wf.x, wf.x));   // k even
                fmaX2(accI2, v.y, pack2(wf.y, wf.y));   // k odd
            }
#pragma unroll
            for (int u = 0; u < 4; u++) w[u] = wn[u];
        }
    }
    // hidden GEMM: same pipeline
    {
        const __half2* Wp = g_WT_hh_h2 + j;
        __half2 w[4];
#pragma unroll
        for (int u = 0; u < 4; u++) w[u] = Wp[u * J3H];
#pragma unroll 1
        for (int k2 = 0; k2 < H / 2; k2 += 4) {
            __half2 wn[4];
#pragma unroll
            for (int u = 0; u < 4; u++) wn[u] = Wp[(k2 + 4 + u) * J3H];
#pragma unroll
            for (int u = 0; u < 4; u++) {
                float2 wf = __half22float2(w[u]);
                ulonglong2 v = *(const ulonglong2*)&hs2[k2 + u][0];
                fmaX2(accH2, v.x, pack2(wf.x, wf.x));
                fmaX2(accH2, v.y, pack2(wf.y, wf.y));
            }
#pragma unroll
            for (int u = 0; u < 4; u++) w[u] = wn[u];
        }
    }

    {
        float2 iacc = unpack2(accI2);
        float2 hacc = unpack2(accH2);
        float accI[GB] = { iacc.x, iacc.y };
        float accH[GB] = { hacc.x, hacc.y };
        if (j < 2 * H) {
#pragma unroll
            for (int bb = 0; bb < GB; bb++) Ssum[bb][j] = accI[bb] + accH[bb];
        } else {
            int jj = j - 2 * H;
#pragma unroll
            for (int bb = 0; bb < GB; bb++) { INs[bb][jj] = accI[bb]; HNs[bb][jj] = accH[bb]; }
        }
    }
    __syncthreads();

    // gates + h update (GB*H = 192 <= 288: single pass)
    if (tid < GB * H) {
        int bb = tid / H, h = tid % H;
        float r = sigmoid_fast(Ssum[bb][h]);
        float z = sigmoid_fast(Ssum[bb][H + h]);
        float n = tanh_fast(INs[bb][h] + r * HNs[bb][h]);
        int slot = (h & 1) * 2 + bb;
        float hn = (1.f - z) * n + z * hs2[h >> 1][slot];
        g_h[(b0 + bb) * H + h] = hn;
        hs2[h >> 1][slot] = hn;   // own slot: read-then-write, race-free
    }
    __syncthreads();

    // generator: probs[b,s,:] = h_new @ w_gen^T + b_gen  (GB*NC = 76 threads)
    if (tid < GB * NC) {
        int bb = tid / NC, nc = tid % NC;
        float acc = b_gen[nc];
#pragma unroll 4
        for (int h = 0; h < H; h++) acc += g_WT_gen[h * NC + nc] * hs2[h >> 1][(h & 1) * 2 + bb];
        probs[(size_t)((b0 + bb) * S + s) * NC + nc] = acc;
    }

    // next-step hp: hp[b] = h_new @ w_h2h^T + b_h2h  (GB*H = 192 threads)
    if (tid < GB * H) {
        int bb = tid / H, h = tid % H;
        float acc = b_h2h[h];
#pragma unroll 4
        for (int k = 0; k < H; k++) acc += g_WT_h2h[k * H + h] * hs2[k >> 1][(k & 1) * 2 + bb];
        g_hp[(b0 + bb) * H + h] = acc;
    }
}

// ---------------- launch ----------------
extern "C" void kernel_launch(void* const* d_in, const int* in_sizes, int n_in,
                              void* d_out, int out_size) {
    const float* inputs  = (const float*)d_in[0];
    const void*  targets = d_in[1];
    const float* w_i2h   = (const float*)d_in[2];
    const float* w_h2h   = (const float*)d_in[3];
    const float* b_h2h   = (const float*)d_in[4];
    const float* w_score = (const float*)d_in[5];
    const float* w_ih    = (const float*)d_in[6];
    const float* w_hh    = (const float*)d_in[7];
    const float* b_ih    = (const float*)d_in[8];
    const float* b_hh    = (const float*)d_in[9];
    const float* w_gen   = (const float*)d_in[10];
    const float* b_gen   = (const float*)d_in[11];
    float* probs = (float*)d_out;

    prep_kernel<<<148, 256>>>(w_i2h, w_h2h, b_h2h, w_ih, w_hh, w_gen, targets);
    hproj_kernel<<<(B * T) / HP_ROWS, 256>>>(inputs);
    for (int s = 0; s < S; s++) {
        att_kernel<<<B, 256>>>(w_score);
        gru_kernel<<<B / GB, J3H>>>(targets, b_ih, b_hh, b_h2h, b_gen, probs, s);
    }
}

// round 14
// speedup vs baseline: 2.4091x; 1.1074x over previous
#include <cuda_runtime.h>
#include <cuda_fp16.h>
#include <cstdint>

#define B 2048
#define T 128
#define C 192
#define H 96
#define NC 38
#define S 25
#define J3H 288        // 3*H
#define KX 230         // C + NC
#define GB 2           // batch items per fused step block

// ---------------- device scratch (no allocations allowed) ----------------
__device__ __half g_Hproj_h[(size_t)B * T * H];   // 50 MB fp16
__device__ __half g_in_h[(size_t)B * T * C];      // 100 MB fp16 copy of inputs
__device__ float g_h[B * H];
__device__ float g_hp[B * H];                     // h @ w_h2h^T + b_h2h, for NEXT att step
__device__ float g_WT_i2h[C * H];                 // [c][h]
__device__ float g_WT_h2h[H * H];                 // [k][h]
__device__ float g_WT_ih[KX * J3H];               // [k][j] fp32 (one-hot gather only)
__device__ __half2 g_WT_ih_h2[(C / 2 + 4) * J3H]; // [k2][j], pair over k, +4 rows prefetch pad
__device__ __half2 g_WT_hh_h2[(H / 2 + 4) * J3H]; // [k2][j], +4 rows prefetch pad
__device__ float g_WT_gen[H * NC];                // [h][nc]
__device__ int   g_is64;

// ---------------- packed fp32x2 helpers (Blackwell) ----------------
__device__ __forceinline__ unsigned long long pack2(float lo, float hi) {
    unsigned long long r;
    asm("mov.b64 %0, {%1, %2};" : "=l"(r) : "f"(lo), "f"(hi));
    return r;
}
__device__ __forceinline__ float2 unpack2(unsigned long long v) {
    float lo, hi;
    asm("mov.b64 {%0, %1}, %2;" : "=f"(lo), "=f"(hi) : "l"(v));
    return make_float2(lo, hi);
}
__device__ __forceinline__ void fmaX2(unsigned long long& d, unsigned long long a, unsigned long long b) {
    asm("fma.rn.f32x2 %0, %1, %2, %0;" : "+l"(d) : "l"(a), "l"(b));
}

// ---------------- fast math helpers ----------------
__device__ __forceinline__ float tanh_mufu(float x) {   // att energy only (~5e-4 abs err)
    float y; asm("tanh.approx.f32 %0, %1;" : "=f"(y) : "f"(x)); return y;
}
__device__ __forceinline__ float tanh_fast(float x) {   // GRU recurrence (precise path)
    x = fminf(fmaxf(x, -10.f), 10.f);
    float e = __expf(2.f * x);
    return __fdividef(e - 1.f, e + 1.f);
}
__device__ __forceinline__ float sigmoid_fast(float x) {
    return __fdividef(1.f, 1.f + __expf(-x));
}

// ---------------- prep: transposes + h/hp init + targets dtype probe ----------------
__global__ void prep_kernel(const float* __restrict__ w_i2h,
                            const float* __restrict__ w_h2h,
                            const float* __restrict__ b_h2h,
                            const float* __restrict__ w_ih,
                            const float* __restrict__ w_hh,
                            const float* __restrict__ w_gen,
                            const void*  __restrict__ targets_raw) {
    int i0 = blockIdx.x * blockDim.x + threadIdx.x;
    int stride = gridDim.x * blockDim.x;
    for (int i = i0; i < H * C; i += stride) { int h = i / C, c = i % C; g_WT_i2h[c * H + h] = w_i2h[i]; }
    for (int i = i0; i < H * H; i += stride) { int h = i / H, k = i % H; g_WT_h2h[k * H + h] = w_h2h[i]; }
    for (int i = i0; i < J3H * KX; i += stride) { int j = i / KX, k = i % KX; g_WT_ih[k * J3H + j] = w_ih[i]; }
    for (int i = i0; i < (C / 2) * J3H; i += stride) {
        int j = i % J3H, k2 = i / J3H;
        g_WT_ih_h2[k2 * J3H + j] = __floats2half2_rn(w_ih[j * KX + 2 * k2], w_ih[j * KX + 2 * k2 + 1]);
    }
    for (int i = i0; i < (H / 2) * J3H; i += stride) {
        int j = i % J3H, k2 = i / J3H;
        g_WT_hh_h2[k2 * J3H + j] = __floats2half2_rn(w_hh[j * H + 2 * k2], w_hh[j * H + 2 * k2 + 1]);
    }
    for (int i = i0; i < 4 * J3H; i += stride) {
        g_WT_ih_h2[(C / 2) * J3H + i] = __floats2half2_rn(0.f, 0.f);
        g_WT_hh_h2[(H / 2) * J3H + i] = __floats2half2_rn(0.f, 0.f);
    }
    for (int i = i0; i < NC * H; i += stride) { int n = i / H, h = i % H; g_WT_gen[h * NC + n] = w_gen[i]; }
    for (int i = i0; i < B * H; i += stride) { g_h[i] = 0.f; g_hp[i] = b_h2h[i % H]; }
    if (i0 == 0) {
        // Detect int64 vs int32 targets: valid int64 class indices are all in [0, NC).
        const long long* t64 = (const long long*)targets_raw;
        int ok = 1;
        for (int q = 0; q < 64; q++) {
            long long v = t64[q];
            if (v < 0 || v >= NC) { ok = 0; break; }
        }
        g_is64 = ok;
    }
}

// ---------------- Hproj = inputs @ w_i2h^T ([B*T, H], fp16 out) + fp16 inputs copy ----------------
#define HP_ROWS 64
#define HP_CK   64
__global__ void __launch_bounds__(256) hproj_kernel(const float* __restrict__ inputs) {
    __shared__ __align__(16) float in_sT[HP_CK][HP_ROWS];   // [cc][r] transposed tile
    __shared__ __align__(16) float wt_s[HP_CK][H];
    int tid = threadIdx.x;
    int tx = tid & 31, ty = tid >> 5;
    int rowbase = blockIdx.x * HP_ROWS;

    unsigned long long accp[4][3];
#pragma unroll
    for (int rp = 0; rp < 4; rp++)
#pragma unroll
        for (int k = 0; k < 3; k++) accp[rp][k] = pack2(0.f, 0.f);

    for (int c0 = 0; c0 < C; c0 += HP_CK) {
        const float4* wsrc = (const float4*)(g_WT_i2h + c0 * H);
        for (int idx = tid; idx < HP_CK * H / 4; idx += 256)
            ((float4*)wt_s)[idx] = wsrc[idx];
        for (int idx = tid; idx < HP_ROWS * HP_CK / 4; idx += 256) {
            int r = idx >> 4;
            int q = idx & 15;
            size_t gidx = (size_t)(rowbase + r) * C + c0 + q * 4;
            float4 v = *(const float4*)(inputs + gidx);
            in_sT[q * 4 + 0][r] = v.x;
            in_sT[q * 4 + 1][r] = v.y;
            in_sT[q * 4 + 2][r] = v.z;
            in_sT[q * 4 + 3][r] = v.w;
            ((__half2*)g_in_h)[gidx / 2]     = __floats2half2_rn(v.x, v.y);
            ((__half2*)g_in_h)[gidx / 2 + 1] = __floats2half2_rn(v.z, v.w);
        }
        __syncthreads();
#pragma unroll 2
        for (int cc = 0; cc < HP_CK; ++cc) {
            unsigned long long W0 = pack2(wt_s[cc][tx * 3 + 0], wt_s[cc][tx * 3 + 0]);
            unsigned long long W1 = pack2(wt_s[cc][tx * 3 + 1], wt_s[cc][tx * 3 + 1]);
            unsigned long long W2 = pack2(wt_s[cc][tx * 3 + 2], wt_s[cc][tx * 3 + 2]);
            const ulonglong2* ivp = (const ulonglong2*)&in_sT[cc][ty * 8];
            ulonglong2 iva = ivp[0], ivb = ivp[1];
            fmaX2(accp[0][0], iva.x, W0); fmaX2(accp[0][1], iva.x, W1); fmaX2(accp[0][2], iva.x, W2);
            fmaX2(accp[1][0], iva.y, W0); fmaX2(accp[1][1], iva.y, W1); fmaX2(accp[1][2], iva.y, W2);
            fmaX2(accp[2][0], ivb.x, W0); fmaX2(accp[2][1], ivb.x, W1); fmaX2(accp[2][2], ivb.x, W2);
            fmaX2(accp[3][0], ivb.y, W0); fmaX2(accp[3][1], ivb.y, W1); fmaX2(accp[3][2], ivb.y, W2);
        }
        __syncthreads();
    }
#pragma unroll
    for (int rp = 0; rp < 4; rp++) {
        float2 a0 = unpack2(accp[rp][0]);
        float2 a1 = unpack2(accp[rp][1]);
        float2 a2 = unpack2(accp[rp][2]);
        __half* d0 = g_Hproj_h + (size_t)(rowbase + ty * 8 + 2 * rp) * H + tx * 3;
        __half* d1 = d0 + H;
        d0[0] = __float2half_rn(a0.x); d0[1] = __float2half_rn(a1.x); d0[2] = __float2half_rn(a2.x);
        d1[0] = __float2half_rn(a0.y); d1[1] = __float2half_rn(a1.y); d1[2] = __float2half_rn(a2.y);
    }
}

// ---------------- fused per-step kernel: attention + GRU for 2 batch items ----------------
__global__ void __launch_bounds__(288, 7) step_kernel(const void* __restrict__ targets_raw,
                                                      const float* __restrict__ w_score,
                                                      const float* __restrict__ b_ih,
                                                      const float* __restrict__ b_hh,
                                                      const float* __restrict__ b_h2h,
                                                      const float* __restrict__ b_gen,
                                                      float* __restrict__ probs, int s) {
    __shared__ float hp_s[GB * H], sv_s[H];
    __shared__ float epart[GB * T][9];               // 8 energy partials per (bb,t), pad to 9
    __shared__ float alpha_s[GB][T];
    __shared__ __align__(16) float xs2[C / 2][4];    // k-pair-packed context (filled locally!)
    __shared__ __align__(16) float hs2[H / 2][4];    // k-pair-packed h (then h_new)
    __shared__ float Ssum[GB][2 * H];
    __shared__ float INs[GB][H];
    __shared__ float HNs[GB][H];
    __shared__ int cls_s[GB];

    int tid = threadIdx.x;
    int w = tid >> 5, l = tid & 31;
    int b0 = blockIdx.x * GB;

    // ---- loads (hp, sv, h, cls) ----
    if (tid < GB * H) hp_s[tid] = g_hp[b0 * H + tid];   // [bb*H + h]
    if (tid < H) sv_s[tid] = w_score[tid];
    for (int idx = tid; idx < GB * H; idx += J3H) {
        int bb = idx / H, k = idx % H;
        hs2[k >> 1][(k & 1) * 2 + bb] = g_h[(b0 + bb) * H + k];
    }
    if (tid < GB) {
        int cls;
        if (g_is64) cls = (int)((const long long*)targets_raw)[(size_t)(b0 + tid) * S + s];
        else        cls = ((const int*)targets_raw)[(size_t)(b0 + tid) * S + s];
        cls_s[tid] = cls;
    }
    __syncthreads();

    // ---- phase A: energy partials. 8 warps: warp w -> bb=w>>2, t-range (w&3)*32..+32 ----
    if (w < 8) {
        int bb = w >> 2, tb = (w & 3) * 32;
        const __half2* hb2 = (const __half2*)(g_Hproj_h + (size_t)(b0 + bb) * T * H);
        const float* hpb = hp_s + bb * H;
#pragma unroll 4
        for (int i = 0; i < 32; i++) {
            int t = tb + i;
            const __half2* row = hb2 + t * (H / 2);
            float2 fa = __half22float2(row[l]);
            float v = sv_s[2 * l]     * tanh_mufu(fa.x + hpb[2 * l])
                    + sv_s[2 * l + 1] * tanh_mufu(fa.y + hpb[2 * l + 1]);
            if (l < 16) {
                float2 fb = __half22float2(row[32 + l]);
                v += sv_s[64 + 2 * l] * tanh_mufu(fb.x + hpb[64 + 2 * l])
                   + sv_s[65 + 2 * l] * tanh_mufu(fb.y + hpb[65 + 2 * l]);
            }
            v += __shfl_xor_sync(0xffffffffu, v, 16);
            v += __shfl_xor_sync(0xffffffffu, v, 8);
            if (l < 8) epart[bb * T + t][l] = v;
        }
    }
    __syncthreads();

    // ---- phase B: softmax, warp 0 -> b0, warp 1 -> b1 ----
    if (w < 2) {
        int bb = w;
        float e[4];
#pragma unroll
        for (int q = 0; q < 4; q++) {
            const float* ep = epart[bb * T + l + 32 * q];
            e[q] = ((ep[0] + ep[1]) + (ep[2] + ep[3])) + ((ep[4] + ep[5]) + (ep[6] + ep[7]));
        }
        float m = fmaxf(fmaxf(e[0], e[1]), fmaxf(e[2], e[3]));
#pragma unroll
        for (int off = 16; off > 0; off >>= 1) m = fmaxf(m, __shfl_xor_sync(0xffffffffu, m, off));
        float p0 = __expf(e[0] - m), p1 = __expf(e[1] - m), p2 = __expf(e[2] - m), p3 = __expf(e[3] - m);
        float ssum = p0 + p1 + p2 + p3;
#pragma unroll
        for (int off = 16; off > 0; off >>= 1) ssum += __shfl_xor_sync(0xffffffffu, ssum, off);
        float inv = __fdividef(1.f, ssum);
        alpha_s[bb][l]      = p0 * inv;
        alpha_s[bb][l + 32] = p1 * inv;
        alpha_s[bb][l + 64] = p2 * inv;
        alpha_s[bb][l + 96] = p3 * inv;
    }
    __syncthreads();

    // ---- phase C: context straight into xs2 (k-pair-packed), 192 threads ----
    if (tid < 192) {
        int bb = tid / 96, col = tid % 96;   // col = half2 column = k-pair index
        const __half2* ip = (const __half2*)g_in_h + (size_t)(b0 + bb) * T * 96 + col;
        float ax = 0.f, ay = 0.f;
#pragma unroll 8
        for (int t = 0; t < T; t++) {
            float2 f = __half22float2(ip[t * 96]);
            float al = alpha_s[bb][t];
            ax += al * f.x; ay += al * f.y;
        }
        xs2[col][bb]     = ax;   // k = 2*col   (even -> slot bb)
        xs2[col][2 + bb] = ay;   // k = 2*col+1 (odd  -> slot 2+bb)
    }
    __syncthreads();

    // ---- phase D: GRU GEMMs ----
    int j = tid;  // 0..287
    unsigned long long accI2 = pack2(b_ih[j] + g_WT_ih[(C + cls_s[0]) * J3H + j],
                                     b_ih[j] + g_WT_ih[(C + cls_s[1]) * J3H + j]);
    float bH = b_hh[j];
    unsigned long long accH2 = pack2(bH, bH);

    {
        const __half2* Wp = g_WT_ih_h2 + j;
        __half2 wv[4];
#pragma unroll
        for (int u = 0; u < 4; u++) wv[u] = Wp[u * J3H];
#pragma unroll 1
        for (int k2 = 0; k2 < C / 2; k2 += 4) {
            __half2 wn[4];
#pragma unroll
            for (int u = 0; u < 4; u++) wn[u] = Wp[(k2 + 4 + u) * J3H];  // pad rows keep in-bounds
#pragma unroll
            for (int u = 0; u < 4; u++) {
                float2 wf = __half22float2(wv[u]);
                ulonglong2 v = *(const ulonglong2*)&xs2[k2 + u][0];
                fmaX2(accI2, v.x, pack2(wf.x, wf.x));
                fmaX2(accI2, v.y, pack2(wf.y, wf.y));
            }
#pragma unroll
            for (int u = 0; u < 4; u++) wv[u] = wn[u];
        }
    }
    {
        const __half2* Wp = g_WT_hh_h2 + j;
        __half2 wv[4];
#pragma unroll
        for (int u = 0; u < 4; u++) wv[u] = Wp[u * J3H];
#pragma unroll 1
        for (int k2 = 0; k2 < H / 2; k2 += 4) {
            __half2 wn[4];
#pragma unroll
            for (int u = 0; u < 4; u++) wn[u] = Wp[(k2 + 4 + u) * J3H];
#pragma unroll
            for (int u = 0; u < 4; u++) {
                float2 wf = __half22float2(wv[u]);
                ulonglong2 v = *(const ulonglong2*)&hs2[k2 + u][0];
                fmaX2(accH2, v.x, pack2(wf.x, wf.x));
                fmaX2(accH2, v.y, pack2(wf.y, wf.y));
            }
#pragma unroll
            for (int u = 0; u < 4; u++) wv[u] = wn[u];
        }
    }

    {
        float2 iacc = unpack2(accI2);
        float2 hacc = unpack2(accH2);
        float accI[GB] = { iacc.x, iacc.y };
        float accH[GB] = { hacc.x, hacc.y };
        if (j < 2 * H) {
#pragma unroll
            for (int bb = 0; bb < GB; bb++) Ssum[bb][j] = accI[bb] + accH[bb];
        } else {
            int jj = j - 2 * H;
#pragma unroll
            for (int bb = 0; bb < GB; bb++) { INs[bb][jj] = accI[bb]; HNs[bb][jj] = accH[bb]; }
        }
    }
    __syncthreads();

    // gates + h update (GB*H = 192 threads)
    if (tid < GB * H) {
        int bb = tid / H, h = tid % H;
        float r = sigmoid_fast(Ssum[bb][h]);
        float z = sigmoid_fast(Ssum[bb][H + h]);
        float n = tanh_fast(INs[bb][h] + r * HNs[bb][h]);
        int slot = (h & 1) * 2 + bb;
        float hn = (1.f - z) * n + z * hs2[h >> 1][slot];
        g_h[(b0 + bb) * H + h] = hn;
        hs2[h >> 1][slot] = hn;   // own slot: read-then-write, race-free
    }
    __syncthreads();

    // generator: probs[b,s,:] = h_new @ w_gen^T + b_gen  (GB*NC = 76 threads)
    if (tid < GB * NC) {
        int bb = tid / NC, nc = tid % NC;
        float acc = b_gen[nc];
#pragma unroll 4
        for (int h = 0; h < H; h++) acc += g_WT_gen[h * NC + nc] * hs2[h >> 1][(h & 1) * 2 + bb];
        probs[(size_t)((b0 + bb) * S + s) * NC + nc] = acc;
    }

    // next-step hp: hp[b] = h_new @ w_h2h^T + b_h2h  (GB*H = 192 threads)
    if (tid < GB * H) {
        int bb = tid / H, h = tid % H;
        float acc = b_h2h[h];
#pragma unroll 4
        for (int k = 0; k < H; k++) acc += g_WT_h2h[k * H + h] * hs2[k >> 1][(k & 1) * 2 + bb];
        g_hp[(b0 + bb) * H + h] = acc;
    }
}

// ---------------- launch ----------------
extern "C" void kernel_launch(void* const* d_in, const int* in_sizes, int n_in,
                              void* d_out, int out_size) {
    const float* inputs  = (const float*)d_in[0];
    const void*  targets = d_in[1];
    const float* w_i2h   = (const float*)d_in[2];
    const float* w_h2h   = (const float*)d_in[3];
    const float* b_h2h   = (const float*)d_in[4];
    const float* w_score = (const float*)d_in[5];
    const float* w_ih    = (const float*)d_in[6];
    const float* w_hh    = (const float*)d_in[7];
    const float* b_ih    = (const float*)d_in[8];
    const float* b_hh    = (const float*)d_in[9];
    const float* w_gen   = (const float*)d_in[10];
    const float* b_gen   = (const float*)d_in[11];
    float* probs = (float*)d_out;

    prep_kernel<<<148, 256>>>(w_i2h, w_h2h, b_h2h, w_ih, w_hh, w_gen, targets);
    hproj_kernel<<<(B * T) / HP_ROWS, 256>>>(inputs);
    for (int s = 0; s < S; s++) {
        step_kernel<<<B / GB, J3H>>>(targets, w_score, b_ih, b_hh, b_h2h, b_gen, probs, s);
    }
}